// round 7
// baseline (speedup 1.0000x reference)
#include <cuda_runtime.h>
#include <cuda_fp16.h>
#include <cstdint>

// B=2, N=2048, D=1024, H=16, HD=64
#define Bc 2
#define Nc 2048
#define Dc 1024
#define Hc 16
#define HDc 64

// ---------------- scratch (fp16 inter-kernel tensors) ----------------
__device__ __half g_q[(size_t)Bc * Hc * Nc * HDc];
__device__ __half g_k[(size_t)Bc * Hc * Nc * HDc];   // pre-scaled by HD^-0.5
__device__ __half g_v[(size_t)Bc * Hc * Nc * HDc];
__device__ __half g_s[(size_t)Bc * Hc * Nc * Nc];    // 268MB, in-place
__device__ __half g_o[(size_t)Bc * Nc * Hc * HDc];

// ---------------- helpers ----------------
__device__ __forceinline__ uint32_t pack2(float a, float b) {
    __half2 h = __floats2half2_rn(a, b);
    return *(uint32_t*)&h;
}
__device__ __forceinline__ void mma16(float& c0, float& c1, float& c2, float& c3,
                                      uint32_t a0, uint32_t a1, uint32_t a2, uint32_t a3,
                                      uint32_t b0, uint32_t b1) {
    asm volatile(
        "mma.sync.aligned.m16n8k16.row.col.f32.f16.f16.f32 "
        "{%0,%1,%2,%3}, {%4,%5,%6,%7}, {%8,%9}, {%0,%1,%2,%3};"
        : "+f"(c0), "+f"(c1), "+f"(c2), "+f"(c3)
        : "r"(a0), "r"(a1), "r"(a2), "r"(a3), "r"(b0), "r"(b1));
}

// =======================================================================
// kernel 1: QKV projections, fp16 MMA, reg-prefetch pipeline.
// Block 128x128, BK=16, 8 warps 2x4.
// =======================================================================
__global__ void __launch_bounds__(256, 2)
proj_f16(const float* __restrict__ x, const float* __restrict__ Wq,
         const float* __restrict__ Wk, const float* __restrict__ Wv) {
    __shared__ uint32_t Ah2[8][132], Bh2[8][132];
    int which = blockIdx.z;
    const float* W = which == 0 ? Wq : (which == 1 ? Wk : Wv);
    __half* dst = which == 0 ? g_q : (which == 1 ? g_k : g_v);
    float scale = (which == 1) ? 0.125f : 1.0f;

    int tid = threadIdx.x, lane = tid & 31, w = tid >> 5;
    int wm = (w & 1) * 64, wn = (w >> 1) * 32;
    int row0 = blockIdx.y * 128, col0 = blockIdx.x * 128;

    // load-index precompute
    int am0 = tid >> 2, ak0 = (tid & 3) * 4;
    int am1 = (tid + 256) >> 2, ak1 = ((tid + 256) & 3) * 4;
    int bkp = tid >> 5, bn4 = (tid & 31) * 4;

    float4 ra0, ra1, rb0, rb1;
    // prefetch kt=0
    ra0 = *(const float4*)&x[(size_t)(row0 + am0) * Dc + ak0];
    ra1 = *(const float4*)&x[(size_t)(row0 + am1) * Dc + ak1];
    rb0 = *(const float4*)&W[(size_t)(2 * bkp) * (Hc * HDc) + col0 + bn4];
    rb1 = *(const float4*)&W[(size_t)(2 * bkp + 1) * (Hc * HDc) + col0 + bn4];

    float acc[4][4][4];
#pragma unroll
    for (int a = 0; a < 4; a++)
#pragma unroll
        for (int b = 0; b < 4; b++)
#pragma unroll
            for (int c = 0; c < 4; c++) acc[a][b][c] = 0.f;

    for (int kt = 0; kt < Dc; kt += 16) {
        // commit regs -> smem
        Ah2[ak0 >> 1][am0] = pack2(ra0.x, ra0.y);
        Ah2[(ak0 >> 1) + 1][am0] = pack2(ra0.z, ra0.w);
        Ah2[ak1 >> 1][am1] = pack2(ra1.x, ra1.y);
        Ah2[(ak1 >> 1) + 1][am1] = pack2(ra1.z, ra1.w);
        uint4 st = {pack2(rb0.x, rb1.x), pack2(rb0.y, rb1.y), pack2(rb0.z, rb1.z), pack2(rb0.w, rb1.w)};
        *(uint4*)&Bh2[bkp][bn4] = st;
        __syncthreads();
        // prefetch next tile (overlaps MMA)
        if (kt + 16 < Dc) {
            ra0 = *(const float4*)&x[(size_t)(row0 + am0) * Dc + kt + 16 + ak0];
            ra1 = *(const float4*)&x[(size_t)(row0 + am1) * Dc + kt + 16 + ak1];
            rb0 = *(const float4*)&W[(size_t)(kt + 16 + 2 * bkp) * (Hc * HDc) + col0 + bn4];
            rb1 = *(const float4*)&W[(size_t)(kt + 16 + 2 * bkp + 1) * (Hc * HDc) + col0 + bn4];
        }
        int kr = lane & 3, rr = lane >> 2;
        uint32_t ah[4][4], bh[4][2];
#pragma unroll
        for (int mi = 0; mi < 4; mi++) {
            int rb = wm + mi * 16 + rr;
            ah[mi][0] = Ah2[kr][rb];
            ah[mi][1] = Ah2[kr][rb + 8];
            ah[mi][2] = Ah2[kr + 4][rb];
            ah[mi][3] = Ah2[kr + 4][rb + 8];
        }
#pragma unroll
        for (int ni = 0; ni < 4; ni++) {
            int nb = wn + ni * 8 + rr;
            bh[ni][0] = Bh2[kr][nb];
            bh[ni][1] = Bh2[kr + 4][nb];
        }
#pragma unroll
        for (int mi = 0; mi < 4; mi++)
#pragma unroll
            for (int ni = 0; ni < 4; ni++) {
                float* c = acc[mi][ni];
                mma16(c[0], c[1], c[2], c[3], ah[mi][0], ah[mi][1], ah[mi][2], ah[mi][3], bh[ni][0], bh[ni][1]);
            }
        __syncthreads();
    }
#pragma unroll
    for (int mi = 0; mi < 4; mi++) {
        int r0 = row0 + wm + mi * 16 + (lane >> 2);
        int r1 = r0 + 8;
        int b0i = r0 >> 11, n0i = r0 & (Nc - 1);
        int b1i = r1 >> 11, n1i = r1 & (Nc - 1);
#pragma unroll
        for (int ni = 0; ni < 4; ni++) {
            int c = col0 + wn + ni * 8 + (lane & 3) * 2;
            int h = c >> 6, d = c & 63;
            __half2 v0 = __floats2half2_rn(acc[mi][ni][0] * scale, acc[mi][ni][1] * scale);
            __half2 v1 = __floats2half2_rn(acc[mi][ni][2] * scale, acc[mi][ni][3] * scale);
            *(__half2*)&dst[(((size_t)b0i * Hc + h) * Nc + n0i) * HDc + d] = v0;
            *(__half2*)&dst[(((size_t)b1i * Hc + h) * Nc + n1i) * HDc + d] = v1;
        }
    }
}

// =======================================================================
// kernel 2: S = Q K^T per (b,h), fp16 MMA, reg-prefetch. Block 128x128, K=64.
// =======================================================================
__global__ void __launch_bounds__(256, 2) scores_f16() {
    __shared__ uint32_t Ah2[8][132], Bh2[8][132];
    int bh_ = blockIdx.z;
    const __half* Q = g_q + (size_t)bh_ * Nc * HDc;
    const __half* Kc = g_k + (size_t)bh_ * Nc * HDc;

    int tid = threadIdx.x, lane = tid & 31, w = tid >> 5;
    int wm = (w & 1) * 64, wn = (w >> 1) * 32;
    int row0 = blockIdx.y * 128, col0 = blockIdx.x * 128;

    int lm = tid >> 1, lko = (tid & 1) * 8;

    uint4 rqa, rkb;
    rqa = *(const uint4*)&Q[(size_t)(row0 + lm) * HDc + lko];
    rkb = *(const uint4*)&Kc[(size_t)(col0 + lm) * HDc + lko];

    float acc[4][4][4];
#pragma unroll
    for (int a = 0; a < 4; a++)
#pragma unroll
        for (int b = 0; b < 4; b++)
#pragma unroll
            for (int c = 0; c < 4; c++) acc[a][b][c] = 0.f;

    for (int kt = 0; kt < HDc; kt += 16) {
        Ah2[(lko >> 1) + 0][lm] = rqa.x;
        Ah2[(lko >> 1) + 1][lm] = rqa.y;
        Ah2[(lko >> 1) + 2][lm] = rqa.z;
        Ah2[(lko >> 1) + 3][lm] = rqa.w;
        Bh2[(lko >> 1) + 0][lm] = rkb.x;
        Bh2[(lko >> 1) + 1][lm] = rkb.y;
        Bh2[(lko >> 1) + 2][lm] = rkb.z;
        Bh2[(lko >> 1) + 3][lm] = rkb.w;
        __syncthreads();
        if (kt + 16 < HDc) {
            rqa = *(const uint4*)&Q[(size_t)(row0 + lm) * HDc + kt + 16 + lko];
            rkb = *(const uint4*)&Kc[(size_t)(col0 + lm) * HDc + kt + 16 + lko];
        }
        int kr = lane & 3, rr = lane >> 2;
        uint32_t ah[4][4], bh[4][2];
#pragma unroll
        for (int mi = 0; mi < 4; mi++) {
            int rb = wm + mi * 16 + rr;
            ah[mi][0] = Ah2[kr][rb];
            ah[mi][1] = Ah2[kr][rb + 8];
            ah[mi][2] = Ah2[kr + 4][rb];
            ah[mi][3] = Ah2[kr + 4][rb + 8];
        }
#pragma unroll
        for (int ni = 0; ni < 4; ni++) {
            int nb = wn + ni * 8 + rr;
            bh[ni][0] = Bh2[kr][nb];
            bh[ni][1] = Bh2[kr + 4][nb];
        }
#pragma unroll
        for (int mi = 0; mi < 4; mi++)
#pragma unroll
            for (int ni = 0; ni < 4; ni++) {
                float* c = acc[mi][ni];
                mma16(c[0], c[1], c[2], c[3], ah[mi][0], ah[mi][1], ah[mi][2], ah[mi][3], bh[ni][0], bh[ni][1]);
            }
        __syncthreads();
    }
    size_t base = (size_t)bh_ * Nc * Nc;
#pragma unroll
    for (int mi = 0; mi < 4; mi++) {
        int r0 = row0 + wm + mi * 16 + (lane >> 2);
        int r1 = r0 + 8;
#pragma unroll
        for (int ni = 0; ni < 4; ni++) {
            int c = col0 + wn + ni * 8 + (lane & 3) * 2;
            *(__half2*)&g_s[base + (size_t)r0 * Nc + c] = __floats2half2_rn(acc[mi][ni][0], acc[mi][ni][1]);
            *(__half2*)&g_s[base + (size_t)r1 * Nc + c] = __floats2half2_rn(acc[mi][ni][2], acc[mi][ni][3]);
        }
    }
}

// ---------------- fast exp on FMA pipe ----------------
__device__ __forceinline__ float exp_fast(float x) {
    float y = fmaxf(x * 1.4426950408889634f, -125.0f);
    float r = y + 12582912.0f;
    int ir = __float_as_int(r) - 0x4B400000;
    float rf = r - 12582912.0f;
    float f = y - rf;
    float p = 1.5403530e-4f;
    p = fmaf(p, f, 1.3333558e-3f);
    p = fmaf(p, f, 9.6181291e-3f);
    p = fmaf(p, f, 5.5504109e-2f);
    p = fmaf(p, f, 2.4022651e-1f);
    p = fmaf(p, f, 6.9314718e-1f);
    p = fmaf(p, f, 1.0f);
    return p * __int_as_float((ir + 127) << 23);
}

// ---------------- kernel 3: L-mix -> exp -> Wm-mix, 2-pass, 512 threads ----------------
// No max-subtraction (logit max ~15; subtract fixed 8.0 — exactly cancels in softmax).
__global__ void __launch_bounds__(512)
talk_kernel(const float* __restrict__ Lm, const float* __restrict__ Wmm) {
    extern __shared__ float s[];                 // [16][2048] fp32
    __shared__ float sL[256], sWp[256];
    __shared__ float red[16 * 16];
    __shared__ float ginv[16];

    int tid = threadIdx.x;                       // 512 threads, 16 warps
    int lane = tid & 31, wid = tid >> 5;
    int bn = blockIdx.x;
    int b = bn >> 11, n = bn & (Nc - 1);
    const size_t HSTRIDE = (size_t)Nc * Nc;
    size_t base = ((size_t)b * Hc) * HSTRIDE + (size_t)n * Nc;

    if (tid < 256) sL[tid] = Lm[tid];
    // fp16 tile -> fp32 smem
    for (int idx = tid; idx < Hc * (Nc / 8); idx += 512) {
        int h = idx >> 8, c8 = (idx & 255) * 8;
        uint4 u = *(const uint4*)&g_s[base + (size_t)h * HSTRIDE + c8];
        float2 f0 = __half22float2(*(__half2*)&u.x);
        float2 f1 = __half22float2(*(__half2*)&u.y);
        float2 f2 = __half22float2(*(__half2*)&u.z);
        float2 f3 = __half22float2(*(__half2*)&u.w);
        float4* d = (float4*)&s[h * Nc + c8];
        d[0] = make_float4(f0.x, f0.y, f1.x, f1.y);
        d[1] = make_float4(f2.x, f2.y, f3.x, f3.y);
    }
    __syncthreads();

    // ---- pass A: p = exp(L*S - 8); store in place; accumulate sums ----
    float lsum[16];
#pragma unroll
    for (int g = 0; g < 16; g++) lsum[g] = 0.f;
    for (int j = 0; j < Nc / 512; j++) {
        int m = tid + j * 512;
        float sv[16], pv[16];
#pragma unroll
        for (int h = 0; h < 16; h++) sv[h] = s[h * Nc + m];
#pragma unroll
        for (int g = 0; g < 16; g++) {
            float t = -8.0f;
#pragma unroll
            for (int h = 0; h < 16; h++) t = fmaf(sL[g * 16 + h], sv[h], t);
            float p = exp_fast(t);
            lsum[g] += p;
            pv[g] = p;
        }
#pragma unroll
        for (int g = 0; g < 16; g++) s[g * Nc + m] = pv[g];
    }
#pragma unroll
    for (int g = 0; g < 16; g++) {
        float v = lsum[g];
        for (int o = 16; o; o >>= 1) v += __shfl_xor_sync(0xFFFFFFFFu, v, o);
        if (lane == 0) red[g * 16 + wid] = v;
    }
    __syncthreads();
    if (tid < 16) {
        float v = 0.f;
#pragma unroll
        for (int w = 0; w < 16; w++) v += red[tid * 16 + w];
        ginv[tid] = 1.0f / v;
    }
    __syncthreads();
    if (tid < 256) sWp[tid] = Wmm[tid] * ginv[tid & 15];
    __syncthreads();

    // ---- pass B: U = Wm'*p, write fp16 ----
    for (int j = 0; j < Nc / 512; j++) {
        int m = tid + j * 512;
        float pv[16];
#pragma unroll
        for (int g = 0; g < 16; g++) pv[g] = s[g * Nc + m];
#pragma unroll
        for (int g2 = 0; g2 < 16; g2++) {
            float u = 0.f;
#pragma unroll
            for (int g = 0; g < 16; g++) u = fmaf(sWp[g2 * 16 + g], pv[g], u);
            g_s[base + (size_t)g2 * HSTRIDE + m] = __float2half_rn(u);
        }
    }
}

// =======================================================================
// kernel 4: O = attn @ V per (b,g), fp16 MMA, reg-prefetch. 128(n)x64(d), K=2048.
// =======================================================================
__global__ void __launch_bounds__(256, 3) av_f16() {
    __shared__ uint32_t Ah2[8][132], Bh2[8][68];
    int bh_ = blockIdx.y;
    const __half* U = g_s + (size_t)bh_ * Nc * Nc;
    const __half* V = g_v + (size_t)bh_ * Nc * HDc;

    int tid = threadIdx.x, lane = tid & 31, w = tid >> 5;
    int wm = (w >> 1) * 32, wn = (w & 1) * 32;
    int row0 = blockIdx.x * 128;

    int lm = tid >> 1, lko = (tid & 1) * 8;
    int vkp = tid >> 3, vd8 = (tid & 7) * 8;

    uint4 rua, rvl, rvh;
    rua = *(const uint4*)&U[(size_t)(row0 + lm) * Nc + lko];
    if (tid < 64) {
        rvl = *(const uint4*)&V[(size_t)(2 * vkp) * HDc + vd8];
        rvh = *(const uint4*)&V[(size_t)(2 * vkp + 1) * HDc + vd8];
    }

    float acc[2][4][4];
#pragma unroll
    for (int a = 0; a < 2; a++)
#pragma unroll
        for (int b = 0; b < 4; b++)
#pragma unroll
            for (int c = 0; c < 4; c++) acc[a][b][c] = 0.f;

    for (int kt = 0; kt < Nc; kt += 16) {
        Ah2[(lko >> 1) + 0][lm] = rua.x;
        Ah2[(lko >> 1) + 1][lm] = rua.y;
        Ah2[(lko >> 1) + 2][lm] = rua.z;
        Ah2[(lko >> 1) + 3][lm] = rua.w;
        if (tid < 64) {
            uint4 s0, s1;
            s0.x = __byte_perm(rvl.x, rvh.x, 0x5410); s0.y = __byte_perm(rvl.x, rvh.x, 0x7632);
            s0.z = __byte_perm(rvl.y, rvh.y, 0x5410); s0.w = __byte_perm(rvl.y, rvh.y, 0x7632);
            s1.x = __byte_perm(rvl.z, rvh.z, 0x5410); s1.y = __byte_perm(rvl.z, rvh.z, 0x7632);
            s1.z = __byte_perm(rvl.w, rvh.w, 0x5410); s1.w = __byte_perm(rvl.w, rvh.w, 0x7632);
            *(uint4*)&Bh2[vkp][vd8] = s0;
            *(uint4*)&Bh2[vkp][vd8 + 4] = s1;
        }
        __syncthreads();
        if (kt + 16 < Nc) {
            rua = *(const uint4*)&U[(size_t)(row0 + lm) * Nc + kt + 16 + lko];
            if (tid < 64) {
                rvl = *(const uint4*)&V[(size_t)(kt + 16 + 2 * vkp) * HDc + vd8];
                rvh = *(const uint4*)&V[(size_t)(kt + 16 + 2 * vkp + 1) * HDc + vd8];
            }
        }
        int kr = lane & 3, rr = lane >> 2;
        uint32_t ah[2][4], bh[4][2];
#pragma unroll
        for (int mi = 0; mi < 2; mi++) {
            int rb = wm + mi * 16 + rr;
            ah[mi][0] = Ah2[kr][rb];
            ah[mi][1] = Ah2[kr][rb + 8];
            ah[mi][2] = Ah2[kr + 4][rb];
            ah[mi][3] = Ah2[kr + 4][rb + 8];
        }
#pragma unroll
        for (int ni = 0; ni < 4; ni++) {
            int nb = wn + ni * 8 + rr;
            bh[ni][0] = Bh2[kr][nb];
            bh[ni][1] = Bh2[kr + 4][nb];
        }
#pragma unroll
        for (int mi = 0; mi < 2; mi++)
#pragma unroll
            for (int ni = 0; ni < 4; ni++) {
                float* c = acc[mi][ni];
                mma16(c[0], c[1], c[2], c[3], ah[mi][0], ah[mi][1], ah[mi][2], ah[mi][3], bh[ni][0], bh[ni][1]);
            }
        __syncthreads();
    }
    int b = bh_ >> 4, g = bh_ & 15;
#pragma unroll
    for (int mi = 0; mi < 2; mi++) {
        int r0 = row0 + wm + mi * 16 + (lane >> 2);
        int r1 = r0 + 8;
#pragma unroll
        for (int ni = 0; ni < 4; ni++) {
            int d = wn + ni * 8 + (lane & 3) * 2;
            *(__half2*)&g_o[((size_t)b * Nc + r0) * (Hc * HDc) + g * HDc + d] =
                __floats2half2_rn(acc[mi][ni][0], acc[mi][ni][1]);
            *(__half2*)&g_o[((size_t)b * Nc + r1) * (Hc * HDc) + g * HDc + d] =
                __floats2half2_rn(acc[mi][ni][2], acc[mi][ni][3]);
        }
    }
}

// =======================================================================
// kernel 5: out = g_o @ Wo + bo, fp16 MMA, reg-prefetch. 128x128, K=1024.
// =======================================================================
__global__ void __launch_bounds__(256, 2)
out_f16(const float* __restrict__ Wo, const float* __restrict__ bo,
        float* __restrict__ out) {
    __shared__ uint32_t Ah2[8][132], Bh2[8][132];
    int tid = threadIdx.x, lane = tid & 31, w = tid >> 5;
    int wm = (w & 1) * 64, wn = (w >> 1) * 32;
    int row0 = blockIdx.y * 128, col0 = blockIdx.x * 128;

    int lm = tid >> 1, lko = (tid & 1) * 8;
    int bkp = tid >> 5, bn4 = (tid & 31) * 4;

    uint4 roa;
    float4 rb0, rb1;
    roa = *(const uint4*)&g_o[(size_t)(row0 + lm) * (Hc * HDc) + lko];
    rb0 = *(const float4*)&Wo[(size_t)(2 * bkp) * Dc + col0 + bn4];
    rb1 = *(const float4*)&Wo[(size_t)(2 * bkp + 1) * Dc + col0 + bn4];

    float acc[4][4][4];
#pragma unroll
    for (int a = 0; a < 4; a++)
#pragma unroll
        for (int b = 0; b < 4; b++)
#pragma unroll
            for (int c = 0; c < 4; c++) acc[a][b][c] = 0.f;

    for (int kt = 0; kt < Hc * HDc; kt += 16) {
        Ah2[(lko >> 1) + 0][lm] = roa.x;
        Ah2[(lko >> 1) + 1][lm] = roa.y;
        Ah2[(lko >> 1) + 2][lm] = roa.z;
        Ah2[(lko >> 1) + 3][lm] = roa.w;
        uint4 st = {pack2(rb0.x, rb1.x), pack2(rb0.y, rb1.y), pack2(rb0.z, rb1.z), pack2(rb0.w, rb1.w)};
        *(uint4*)&Bh2[bkp][bn4] = st;
        __syncthreads();
        if (kt + 16 < Hc * HDc) {
            roa = *(const uint4*)&g_o[(size_t)(row0 + lm) * (Hc * HDc) + kt + 16 + lko];
            rb0 = *(const float4*)&Wo[(size_t)(kt + 16 + 2 * bkp) * Dc + col0 + bn4];
            rb1 = *(const float4*)&Wo[(size_t)(kt + 16 + 2 * bkp + 1) * Dc + col0 + bn4];
        }
        int kr = lane & 3, rr = lane >> 2;
        uint32_t ah[4][4], bh[4][2];
#pragma unroll
        for (int mi = 0; mi < 4; mi++) {
            int rb = wm + mi * 16 + rr;
            ah[mi][0] = Ah2[kr][rb];
            ah[mi][1] = Ah2[kr][rb + 8];
            ah[mi][2] = Ah2[kr + 4][rb];
            ah[mi][3] = Ah2[kr + 4][rb + 8];
        }
#pragma unroll
        for (int ni = 0; ni < 4; ni++) {
            int nb = wn + ni * 8 + rr;
            bh[ni][0] = Bh2[kr][nb];
            bh[ni][1] = Bh2[kr + 4][nb];
        }
#pragma unroll
        for (int mi = 0; mi < 4; mi++)
#pragma unroll
            for (int ni = 0; ni < 4; ni++) {
                float* c = acc[mi][ni];
                mma16(c[0], c[1], c[2], c[3], ah[mi][0], ah[mi][1], ah[mi][2], ah[mi][3], bh[ni][0], bh[ni][1]);
            }
        __syncthreads();
    }
#pragma unroll
    for (int mi = 0; mi < 4; mi++) {
        int r0 = row0 + wm + mi * 16 + (lane >> 2);
        int r1 = r0 + 8;
#pragma unroll
        for (int ni = 0; ni < 4; ni++) {
            int c = col0 + wn + ni * 8 + (lane & 3) * 2;
            float2 bias = {bo[c], bo[c + 1]};
            float2 v0 = {acc[mi][ni][0] + bias.x, acc[mi][ni][1] + bias.y};
            float2 v1 = {acc[mi][ni][2] + bias.x, acc[mi][ni][3] + bias.y};
            *(float2*)&out[(size_t)r0 * Dc + c] = v0;
            *(float2*)&out[(size_t)r1 * Dc + c] = v1;
        }
    }
}

// ---------------- launch ----------------
extern "C" void kernel_launch(void* const* d_in, const int* in_sizes, int n_in,
                              void* d_out, int out_size) {
    const float* x  = (const float*)d_in[0];
    const float* Wq = (const float*)d_in[1];
    const float* Wk = (const float*)d_in[2];
    const float* Wv = (const float*)d_in[3];
    const float* L  = (const float*)d_in[4];
    const float* Wm = (const float*)d_in[5];
    const float* Wo = (const float*)d_in[6];
    const float* bo = (const float*)d_in[7];
    float* out = (float*)d_out;
    (void)in_sizes; (void)n_in; (void)out_size;

    proj_f16<<<dim3((Hc * HDc) / 128, (Bc * Nc) / 128, 3), 256>>>(x, Wq, Wk, Wv);

    scores_f16<<<dim3(Nc / 128, Nc / 128, Bc * Hc), 256>>>();

    const int TALK_SMEM = Hc * Nc * sizeof(float);  // 128KB
    (void)cudaFuncSetAttribute(talk_kernel, cudaFuncAttributeMaxDynamicSharedMemorySize, TALK_SMEM);
    talk_kernel<<<Bc * Nc, 512, TALK_SMEM>>>(L, Wm);

    av_f16<<<dim3(Nc / 128, Bc * Hc), 256>>>();

    out_f16<<<dim3(Dc / 128, (Bc * Nc) / 128), 256>>>(Wo, bo, out);
}

// round 9
// speedup vs baseline: 1.8889x; 1.8889x over previous
#include <cuda_runtime.h>
#include <cuda_fp16.h>
#include <cstdint>

// B=2, N=2048, D=1024, H=16, HD=64
#define Bc 2
#define Nc 2048
#define Dc 1024
#define Hc 16
#define HDc 64

// ---------------- scratch (fp16 inter-kernel tensors) ----------------
__device__ __half g_q[(size_t)Bc * Hc * Nc * HDc];
__device__ __half g_k[(size_t)Bc * Hc * Nc * HDc];   // pre-scaled by HD^-0.5
__device__ __half g_v[(size_t)Bc * Hc * Nc * HDc];
__device__ __half g_s[(size_t)Bc * Hc * Nc * Nc];    // 268MB, in-place
__device__ __half g_o[(size_t)Bc * Nc * Hc * HDc];

// ---------------- helpers ----------------
__device__ __forceinline__ uint32_t pack2(float a, float b) {
    __half2 h = __floats2half2_rn(a, b);
    return *(uint32_t*)&h;
}
__device__ __forceinline__ void mma16(float& c0, float& c1, float& c2, float& c3,
                                      uint32_t a0, uint32_t a1, uint32_t a2, uint32_t a3,
                                      uint32_t b0, uint32_t b1) {
    asm volatile(
        "mma.sync.aligned.m16n8k16.row.col.f32.f16.f16.f32 "
        "{%0,%1,%2,%3}, {%4,%5,%6,%7}, {%8,%9}, {%0,%1,%2,%3};"
        : "+f"(c0), "+f"(c1), "+f"(c2), "+f"(c3)
        : "r"(a0), "r"(a1), "r"(a2), "r"(a3), "r"(b0), "r"(b1));
}

// =======================================================================
// kernel 1: QKV projections, fp16 MMA, reg-prefetch pipeline.
// Block 128x128, BK=16, 8 warps 2x4.
// =======================================================================
__global__ void __launch_bounds__(256, 2)
proj_f16(const float* __restrict__ x, const float* __restrict__ Wq,
         const float* __restrict__ Wk, const float* __restrict__ Wv) {
    __shared__ uint32_t Ah2[8][132], Bh2[8][132];
    int which = blockIdx.z;
    const float* W = which == 0 ? Wq : (which == 1 ? Wk : Wv);
    __half* dst = which == 0 ? g_q : (which == 1 ? g_k : g_v);
    float scale = (which == 1) ? 0.125f : 1.0f;

    int tid = threadIdx.x, lane = tid & 31, w = tid >> 5;
    int wm = (w & 1) * 64, wn = (w >> 1) * 32;
    int row0 = blockIdx.y * 128, col0 = blockIdx.x * 128;

    int am0 = tid >> 2, ak0 = (tid & 3) * 4;
    int am1 = (tid + 256) >> 2, ak1 = ((tid + 256) & 3) * 4;
    int bkp = tid >> 5, bn4 = (tid & 31) * 4;

    float4 ra0, ra1, rb0, rb1;
    ra0 = *(const float4*)&x[(size_t)(row0 + am0) * Dc + ak0];
    ra1 = *(const float4*)&x[(size_t)(row0 + am1) * Dc + ak1];
    rb0 = *(const float4*)&W[(size_t)(2 * bkp) * (Hc * HDc) + col0 + bn4];
    rb1 = *(const float4*)&W[(size_t)(2 * bkp + 1) * (Hc * HDc) + col0 + bn4];

    float acc[4][4][4];
#pragma unroll
    for (int a = 0; a < 4; a++)
#pragma unroll
        for (int b = 0; b < 4; b++)
#pragma unroll
            for (int c = 0; c < 4; c++) acc[a][b][c] = 0.f;

    for (int kt = 0; kt < Dc; kt += 16) {
        Ah2[ak0 >> 1][am0] = pack2(ra0.x, ra0.y);
        Ah2[(ak0 >> 1) + 1][am0] = pack2(ra0.z, ra0.w);
        Ah2[ak1 >> 1][am1] = pack2(ra1.x, ra1.y);
        Ah2[(ak1 >> 1) + 1][am1] = pack2(ra1.z, ra1.w);
        uint4 st = {pack2(rb0.x, rb1.x), pack2(rb0.y, rb1.y), pack2(rb0.z, rb1.z), pack2(rb0.w, rb1.w)};
        *(uint4*)&Bh2[bkp][bn4] = st;
        __syncthreads();
        if (kt + 16 < Dc) {
            ra0 = *(const float4*)&x[(size_t)(row0 + am0) * Dc + kt + 16 + ak0];
            ra1 = *(const float4*)&x[(size_t)(row0 + am1) * Dc + kt + 16 + ak1];
            rb0 = *(const float4*)&W[(size_t)(kt + 16 + 2 * bkp) * (Hc * HDc) + col0 + bn4];
            rb1 = *(const float4*)&W[(size_t)(kt + 16 + 2 * bkp + 1) * (Hc * HDc) + col0 + bn4];
        }
        int kr = lane & 3, rr = lane >> 2;
        uint32_t ah[4][4], bh[4][2];
#pragma unroll
        for (int mi = 0; mi < 4; mi++) {
            int rb = wm + mi * 16 + rr;
            ah[mi][0] = Ah2[kr][rb];
            ah[mi][1] = Ah2[kr][rb + 8];
            ah[mi][2] = Ah2[kr + 4][rb];
            ah[mi][3] = Ah2[kr + 4][rb + 8];
        }
#pragma unroll
        for (int ni = 0; ni < 4; ni++) {
            int nb = wn + ni * 8 + rr;
            bh[ni][0] = Bh2[kr][nb];
            bh[ni][1] = Bh2[kr + 4][nb];
        }
#pragma unroll
        for (int mi = 0; mi < 4; mi++)
#pragma unroll
            for (int ni = 0; ni < 4; ni++) {
                float* c = acc[mi][ni];
                mma16(c[0], c[1], c[2], c[3], ah[mi][0], ah[mi][1], ah[mi][2], ah[mi][3], bh[ni][0], bh[ni][1]);
            }
        __syncthreads();
    }
#pragma unroll
    for (int mi = 0; mi < 4; mi++) {
        int r0 = row0 + wm + mi * 16 + (lane >> 2);
        int r1 = r0 + 8;
        int b0i = r0 >> 11, n0i = r0 & (Nc - 1);
        int b1i = r1 >> 11, n1i = r1 & (Nc - 1);
#pragma unroll
        for (int ni = 0; ni < 4; ni++) {
            int c = col0 + wn + ni * 8 + (lane & 3) * 2;
            int h = c >> 6, d = c & 63;
            __half2 v0 = __floats2half2_rn(acc[mi][ni][0] * scale, acc[mi][ni][1] * scale);
            __half2 v1 = __floats2half2_rn(acc[mi][ni][2] * scale, acc[mi][ni][3] * scale);
            *(__half2*)&dst[(((size_t)b0i * Hc + h) * Nc + n0i) * HDc + d] = v0;
            *(__half2*)&dst[(((size_t)b1i * Hc + h) * Nc + n1i) * HDc + d] = v1;
        }
    }
}

// =======================================================================
// kernel 2: S = Q K^T per (b,h), fp16 MMA, reg-prefetch. Block 128x128, K=64.
// =======================================================================
__global__ void __launch_bounds__(256, 2) scores_f16() {
    __shared__ uint32_t Ah2[8][132], Bh2[8][132];
    int bh_ = blockIdx.z;
    const __half* Q = g_q + (size_t)bh_ * Nc * HDc;
    const __half* Kc = g_k + (size_t)bh_ * Nc * HDc;

    int tid = threadIdx.x, lane = tid & 31, w = tid >> 5;
    int wm = (w & 1) * 64, wn = (w >> 1) * 32;
    int row0 = blockIdx.y * 128, col0 = blockIdx.x * 128;

    int lm = tid >> 1, lko = (tid & 1) * 8;

    uint4 rqa, rkb;
    rqa = *(const uint4*)&Q[(size_t)(row0 + lm) * HDc + lko];
    rkb = *(const uint4*)&Kc[(size_t)(col0 + lm) * HDc + lko];

    float acc[4][4][4];
#pragma unroll
    for (int a = 0; a < 4; a++)
#pragma unroll
        for (int b = 0; b < 4; b++)
#pragma unroll
            for (int c = 0; c < 4; c++) acc[a][b][c] = 0.f;

    for (int kt = 0; kt < HDc; kt += 16) {
        Ah2[(lko >> 1) + 0][lm] = rqa.x;
        Ah2[(lko >> 1) + 1][lm] = rqa.y;
        Ah2[(lko >> 1) + 2][lm] = rqa.z;
        Ah2[(lko >> 1) + 3][lm] = rqa.w;
        Bh2[(lko >> 1) + 0][lm] = rkb.x;
        Bh2[(lko >> 1) + 1][lm] = rkb.y;
        Bh2[(lko >> 1) + 2][lm] = rkb.z;
        Bh2[(lko >> 1) + 3][lm] = rkb.w;
        __syncthreads();
        if (kt + 16 < HDc) {
            rqa = *(const uint4*)&Q[(size_t)(row0 + lm) * HDc + kt + 16 + lko];
            rkb = *(const uint4*)&Kc[(size_t)(col0 + lm) * HDc + kt + 16 + lko];
        }
        int kr = lane & 3, rr = lane >> 2;
        uint32_t ah[4][4], bh[4][2];
#pragma unroll
        for (int mi = 0; mi < 4; mi++) {
            int rb = wm + mi * 16 + rr;
            ah[mi][0] = Ah2[kr][rb];
            ah[mi][1] = Ah2[kr][rb + 8];
            ah[mi][2] = Ah2[kr + 4][rb];
            ah[mi][3] = Ah2[kr + 4][rb + 8];
        }
#pragma unroll
        for (int ni = 0; ni < 4; ni++) {
            int nb = wn + ni * 8 + rr;
            bh[ni][0] = Bh2[kr][nb];
            bh[ni][1] = Bh2[kr + 4][nb];
        }
#pragma unroll
        for (int mi = 0; mi < 4; mi++)
#pragma unroll
            for (int ni = 0; ni < 4; ni++) {
                float* c = acc[mi][ni];
                mma16(c[0], c[1], c[2], c[3], ah[mi][0], ah[mi][1], ah[mi][2], ah[mi][3], bh[ni][0], bh[ni][1]);
            }
        __syncthreads();
    }
    size_t base = (size_t)bh_ * Nc * Nc;
#pragma unroll
    for (int mi = 0; mi < 4; mi++) {
        int r0 = row0 + wm + mi * 16 + (lane >> 2);
        int r1 = r0 + 8;
#pragma unroll
        for (int ni = 0; ni < 4; ni++) {
            int c = col0 + wn + ni * 8 + (lane & 3) * 2;
            *(__half2*)&g_s[base + (size_t)r0 * Nc + c] = __floats2half2_rn(acc[mi][ni][0], acc[mi][ni][1]);
            *(__half2*)&g_s[base + (size_t)r1 * Nc + c] = __floats2half2_rn(acc[mi][ni][2], acc[mi][ni][3]);
        }
    }
}

// ---------------- fast exp on FMA pipe ----------------
__device__ __forceinline__ float exp_fast(float x) {
    float y = fmaxf(x * 1.4426950408889634f, -125.0f);
    float r = y + 12582912.0f;
    int ir = __float_as_int(r) - 0x4B400000;
    float rf = r - 12582912.0f;
    float f = y - rf;
    float p = 1.5403530e-4f;
    p = fmaf(p, f, 1.3333558e-3f);
    p = fmaf(p, f, 9.6181291e-3f);
    p = fmaf(p, f, 5.5504109e-2f);
    p = fmaf(p, f, 2.4022651e-1f);
    p = fmaf(p, f, 6.9314718e-1f);
    p = fmaf(p, f, 1.0f);
    return p * __int_as_float((ir + 127) << 23);
}

// ---------------- kernel 3: L-mix -> exp -> Wm-mix, 2-pass, 256 threads ----------------
// Fixed -8 shift instead of row max (cancels exactly in softmax; logits bounded ~20).
// 256 threads: keeps sv/pv/lsum arrays in registers (512 thr forced spills -> R7 regression).
__global__ void __launch_bounds__(256)
talk_kernel(const float* __restrict__ Lm, const float* __restrict__ Wmm) {
    extern __shared__ float s[];                 // [16][2048] fp32
    __shared__ float sL[256], sWp[256];
    __shared__ float red[16 * 8];
    __shared__ float ginv[16];

    int tid = threadIdx.x;                       // 256 threads, 8 warps
    int lane = tid & 31, wid = tid >> 5;
    int bn = blockIdx.x;
    int b = bn >> 11, n = bn & (Nc - 1);
    const size_t HSTRIDE = (size_t)Nc * Nc;
    size_t base = ((size_t)b * Hc) * HSTRIDE + (size_t)n * Nc;

    sL[tid] = Lm[tid];
    // fp16 tile -> fp32 smem
    for (int idx = tid; idx < Hc * (Nc / 8); idx += 256) {
        int h = idx >> 8, c8 = (idx & 255) * 8;
        uint4 u = *(const uint4*)&g_s[base + (size_t)h * HSTRIDE + c8];
        float2 f0 = __half22float2(*(__half2*)&u.x);
        float2 f1 = __half22float2(*(__half2*)&u.y);
        float2 f2 = __half22float2(*(__half2*)&u.z);
        float2 f3 = __half22float2(*(__half2*)&u.w);
        float4* d = (float4*)&s[h * Nc + c8];
        d[0] = make_float4(f0.x, f0.y, f1.x, f1.y);
        d[1] = make_float4(f2.x, f2.y, f3.x, f3.y);
    }
    __syncthreads();

    // ---- pass A: p = exp(L*S - 8); store in place; accumulate sums ----
    float lsum[16];
#pragma unroll
    for (int g = 0; g < 16; g++) lsum[g] = 0.f;
    for (int j = 0; j < Nc / 256; j++) {
        int m = tid + j * 256;
        float sv[16], pv[16];
#pragma unroll
        for (int h = 0; h < 16; h++) sv[h] = s[h * Nc + m];
#pragma unroll
        for (int g = 0; g < 16; g++) {
            float t = -8.0f;
#pragma unroll
            for (int h = 0; h < 16; h++) t = fmaf(sL[g * 16 + h], sv[h], t);
            float p = exp_fast(t);
            lsum[g] += p;
            pv[g] = p;
        }
#pragma unroll
        for (int g = 0; g < 16; g++) s[g * Nc + m] = pv[g];
    }
#pragma unroll
    for (int g = 0; g < 16; g++) {
        float v = lsum[g];
        for (int o = 16; o; o >>= 1) v += __shfl_xor_sync(0xFFFFFFFFu, v, o);
        if (lane == 0) red[g * 8 + wid] = v;
    }
    __syncthreads();
    if (tid < 16) {
        float v = 0.f;
#pragma unroll
        for (int w = 0; w < 8; w++) v += red[tid * 8 + w];
        ginv[tid] = 1.0f / v;
    }
    __syncthreads();
    sWp[tid] = Wmm[tid] * ginv[tid & 15];
    __syncthreads();

    // ---- pass B: U = Wm'*p, write fp16 ----
    for (int j = 0; j < Nc / 256; j++) {
        int m = tid + j * 256;
        float pv[16];
#pragma unroll
        for (int g = 0; g < 16; g++) pv[g] = s[g * Nc + m];
#pragma unroll
        for (int g2 = 0; g2 < 16; g2++) {
            float u = 0.f;
#pragma unroll
            for (int g = 0; g < 16; g++) u = fmaf(sWp[g2 * 16 + g], pv[g], u);
            g_s[base + (size_t)g2 * HSTRIDE + m] = __float2half_rn(u);
        }
    }
}

// =======================================================================
// kernel 4: O = attn @ V per (b,g), fp16 MMA, reg-prefetch. 128(n)x64(d), K=2048.
// =======================================================================
__global__ void __launch_bounds__(256, 3) av_f16() {
    __shared__ uint32_t Ah2[8][132], Bh2[8][68];
    int bh_ = blockIdx.y;
    const __half* U = g_s + (size_t)bh_ * Nc * Nc;
    const __half* V = g_v + (size_t)bh_ * Nc * HDc;

    int tid = threadIdx.x, lane = tid & 31, w = tid >> 5;
    int wm = (w >> 1) * 32, wn = (w & 1) * 32;
    int row0 = blockIdx.x * 128;

    int lm = tid >> 1, lko = (tid & 1) * 8;
    int vkp = tid >> 3, vd8 = (tid & 7) * 8;

    uint4 rua, rvl, rvh;
    rua = *(const uint4*)&U[(size_t)(row0 + lm) * Nc + lko];
    if (tid < 64) {
        rvl = *(const uint4*)&V[(size_t)(2 * vkp) * HDc + vd8];
        rvh = *(const uint4*)&V[(size_t)(2 * vkp + 1) * HDc + vd8];
    }

    float acc[2][4][4];
#pragma unroll
    for (int a = 0; a < 2; a++)
#pragma unroll
        for (int b = 0; b < 4; b++)
#pragma unroll
            for (int c = 0; c < 4; c++) acc[a][b][c] = 0.f;

    for (int kt = 0; kt < Nc; kt += 16) {
        Ah2[(lko >> 1) + 0][lm] = rua.x;
        Ah2[(lko >> 1) + 1][lm] = rua.y;
        Ah2[(lko >> 1) + 2][lm] = rua.z;
        Ah2[(lko >> 1) + 3][lm] = rua.w;
        if (tid < 64) {
            uint4 s0, s1;
            s0.x = __byte_perm(rvl.x, rvh.x, 0x5410); s0.y = __byte_perm(rvl.x, rvh.x, 0x7632);
            s0.z = __byte_perm(rvl.y, rvh.y, 0x5410); s0.w = __byte_perm(rvl.y, rvh.y, 0x7632);
            s1.x = __byte_perm(rvl.z, rvh.z, 0x5410); s1.y = __byte_perm(rvl.z, rvh.z, 0x7632);
            s1.z = __byte_perm(rvl.w, rvh.w, 0x5410); s1.w = __byte_perm(rvl.w, rvh.w, 0x7632);
            *(uint4*)&Bh2[vkp][vd8] = s0;
            *(uint4*)&Bh2[vkp][vd8 + 4] = s1;
        }
        __syncthreads();
        if (kt + 16 < Nc) {
            rua = *(const uint4*)&U[(size_t)(row0 + lm) * Nc + kt + 16 + lko];
            if (tid < 64) {
                rvl = *(const uint4*)&V[(size_t)(kt + 16 + 2 * vkp) * HDc + vd8];
                rvh = *(const uint4*)&V[(size_t)(kt + 16 + 2 * vkp + 1) * HDc + vd8];
            }
        }
        int kr = lane & 3, rr = lane >> 2;
        uint32_t ah[2][4], bh[4][2];
#pragma unroll
        for (int mi = 0; mi < 2; mi++) {
            int rb = wm + mi * 16 + rr;
            ah[mi][0] = Ah2[kr][rb];
            ah[mi][1] = Ah2[kr][rb + 8];
            ah[mi][2] = Ah2[kr + 4][rb];
            ah[mi][3] = Ah2[kr + 4][rb + 8];
        }
#pragma unroll
        for (int ni = 0; ni < 4; ni++) {
            int nb = wn + ni * 8 + rr;
            bh[ni][0] = Bh2[kr][nb];
            bh[ni][1] = Bh2[kr + 4][nb];
        }
#pragma unroll
        for (int mi = 0; mi < 2; mi++)
#pragma unroll
            for (int ni = 0; ni < 4; ni++) {
                float* c = acc[mi][ni];
                mma16(c[0], c[1], c[2], c[3], ah[mi][0], ah[mi][1], ah[mi][2], ah[mi][3], bh[ni][0], bh[ni][1]);
            }
        __syncthreads();
    }
    int b = bh_ >> 4, g = bh_ & 15;
#pragma unroll
    for (int mi = 0; mi < 2; mi++) {
        int r0 = row0 + wm + mi * 16 + (lane >> 2);
        int r1 = r0 + 8;
#pragma unroll
        for (int ni = 0; ni < 4; ni++) {
            int d = wn + ni * 8 + (lane & 3) * 2;
            *(__half2*)&g_o[((size_t)b * Nc + r0) * (Hc * HDc) + g * HDc + d] =
                __floats2half2_rn(acc[mi][ni][0], acc[mi][ni][1]);
            *(__half2*)&g_o[((size_t)b * Nc + r1) * (Hc * HDc) + g * HDc + d] =
                __floats2half2_rn(acc[mi][ni][2], acc[mi][ni][3]);
        }
    }
}

// =======================================================================
// kernel 5: out = g_o @ Wo + bo, fp16 MMA, reg-prefetch. 128x128, K=1024.
// =======================================================================
__global__ void __launch_bounds__(256, 2)
out_f16(const float* __restrict__ Wo, const float* __restrict__ bo,
        float* __restrict__ out) {
    __shared__ uint32_t Ah2[8][132], Bh2[8][132];
    int tid = threadIdx.x, lane = tid & 31, w = tid >> 5;
    int wm = (w & 1) * 64, wn = (w >> 1) * 32;
    int row0 = blockIdx.y * 128, col0 = blockIdx.x * 128;

    int lm = tid >> 1, lko = (tid & 1) * 8;
    int bkp = tid >> 5, bn4 = (tid & 31) * 4;

    uint4 roa;
    float4 rb0, rb1;
    roa = *(const uint4*)&g_o[(size_t)(row0 + lm) * (Hc * HDc) + lko];
    rb0 = *(const float4*)&Wo[(size_t)(2 * bkp) * Dc + col0 + bn4];
    rb1 = *(const float4*)&Wo[(size_t)(2 * bkp + 1) * Dc + col0 + bn4];

    float acc[4][4][4];
#pragma unroll
    for (int a = 0; a < 4; a++)
#pragma unroll
        for (int b = 0; b < 4; b++)
#pragma unroll
            for (int c = 0; c < 4; c++) acc[a][b][c] = 0.f;

    for (int kt = 0; kt < Hc * HDc; kt += 16) {
        Ah2[(lko >> 1) + 0][lm] = roa.x;
        Ah2[(lko >> 1) + 1][lm] = roa.y;
        Ah2[(lko >> 1) + 2][lm] = roa.z;
        Ah2[(lko >> 1) + 3][lm] = roa.w;
        uint4 st = {pack2(rb0.x, rb1.x), pack2(rb0.y, rb1.y), pack2(rb0.z, rb1.z), pack2(rb0.w, rb1.w)};
        *(uint4*)&Bh2[bkp][bn4] = st;
        __syncthreads();
        if (kt + 16 < Hc * HDc) {
            roa = *(const uint4*)&g_o[(size_t)(row0 + lm) * (Hc * HDc) + kt + 16 + lko];
            rb0 = *(const float4*)&Wo[(size_t)(kt + 16 + 2 * bkp) * Dc + col0 + bn4];
            rb1 = *(const float4*)&Wo[(size_t)(kt + 16 + 2 * bkp + 1) * Dc + col0 + bn4];
        }
        int kr = lane & 3, rr = lane >> 2;
        uint32_t ah[4][4], bh[4][2];
#pragma unroll
        for (int mi = 0; mi < 4; mi++) {
            int rb = wm + mi * 16 + rr;
            ah[mi][0] = Ah2[kr][rb];
            ah[mi][1] = Ah2[kr][rb + 8];
            ah[mi][2] = Ah2[kr + 4][rb];
            ah[mi][3] = Ah2[kr + 4][rb + 8];
        }
#pragma unroll
        for (int ni = 0; ni < 4; ni++) {
            int nb = wn + ni * 8 + rr;
            bh[ni][0] = Bh2[kr][nb];
            bh[ni][1] = Bh2[kr + 4][nb];
        }
#pragma unroll
        for (int mi = 0; mi < 4; mi++)
#pragma unroll
            for (int ni = 0; ni < 4; ni++) {
                float* c = acc[mi][ni];
                mma16(c[0], c[1], c[2], c[3], ah[mi][0], ah[mi][1], ah[mi][2], ah[mi][3], bh[ni][0], bh[ni][1]);
            }
        __syncthreads();
    }
#pragma unroll
    for (int mi = 0; mi < 4; mi++) {
        int r0 = row0 + wm + mi * 16 + (lane >> 2);
        int r1 = r0 + 8;
#pragma unroll
        for (int ni = 0; ni < 4; ni++) {
            int c = col0 + wn + ni * 8 + (lane & 3) * 2;
            float2 bias = {bo[c], bo[c + 1]};
            float2 v0 = {acc[mi][ni][0] + bias.x, acc[mi][ni][1] + bias.y};
            float2 v1 = {acc[mi][ni][2] + bias.x, acc[mi][ni][3] + bias.y};
            *(float2*)&out[(size_t)r0 * Dc + c] = v0;
            *(float2*)&out[(size_t)r1 * Dc + c] = v1;
        }
    }
}

// ---------------- launch ----------------
extern "C" void kernel_launch(void* const* d_in, const int* in_sizes, int n_in,
                              void* d_out, int out_size) {
    const float* x  = (const float*)d_in[0];
    const float* Wq = (const float*)d_in[1];
    const float* Wk = (const float*)d_in[2];
    const float* Wv = (const float*)d_in[3];
    const float* L  = (const float*)d_in[4];
    const float* Wm = (const float*)d_in[5];
    const float* Wo = (const float*)d_in[6];
    const float* bo = (const float*)d_in[7];
    float* out = (float*)d_out;
    (void)in_sizes; (void)n_in; (void)out_size;

    proj_f16<<<dim3((Hc * HDc) / 128, (Bc * Nc) / 128, 3), 256>>>(x, Wq, Wk, Wv);

    scores_f16<<<dim3(Nc / 128, Nc / 128, Bc * Hc), 256>>>();

    const int TALK_SMEM = Hc * Nc * sizeof(float);  // 128KB
    (void)cudaFuncSetAttribute(talk_kernel, cudaFuncAttributeMaxDynamicSharedMemorySize, TALK_SMEM);
    talk_kernel<<<Bc * Nc, 256, TALK_SMEM>>>(L, Wm);

    av_f16<<<dim3(Nc / 128, Bc * Hc), 256>>>();

    out_f16<<<dim3(Dc / 128, (Bc * Nc) / 128), 256>>>(Wo, bo, out);
}

// round 10
// speedup vs baseline: 2.0514x; 1.0860x over previous
#include <cuda_runtime.h>
#include <cuda_fp16.h>
#include <cstdint>

// B=2, N=2048, D=1024, H=16, HD=64
#define Bc 2
#define Nc 2048
#define Dc 1024
#define Hc 16
#define HDc 64

// ---------------- scratch (fp16 inter-kernel tensors) ----------------
__device__ __half g_q[(size_t)Bc * Hc * Nc * HDc];
__device__ __half g_k[(size_t)Bc * Hc * Nc * HDc];   // pre-scaled by HD^-0.5
__device__ __half g_v[(size_t)Bc * Hc * Nc * HDc];   // TRANSPOSED: [b,h,d,n]
__device__ __half g_s[(size_t)Bc * Hc * Nc * Nc];    // 268MB, in-place
__device__ __half g_o[(size_t)Bc * Nc * Hc * HDc];

// ---------------- helpers ----------------
__device__ __forceinline__ uint32_t pack2(float a, float b) {
    __half2 h = __floats2half2_rn(a, b);
    return *(uint32_t*)&h;
}
__device__ __forceinline__ void mma16(float& c0, float& c1, float& c2, float& c3,
                                      uint32_t a0, uint32_t a1, uint32_t a2, uint32_t a3,
                                      uint32_t b0, uint32_t b1) {
    asm volatile(
        "mma.sync.aligned.m16n8k16.row.col.f32.f16.f16.f32 "
        "{%0,%1,%2,%3}, {%4,%5,%6,%7}, {%8,%9}, {%0,%1,%2,%3};"
        : "+f"(c0), "+f"(c1), "+f"(c2), "+f"(c3)
        : "r"(a0), "r"(a1), "r"(a2), "r"(a3), "r"(b0), "r"(b1));
}
__device__ __forceinline__ void cpa16(void* dst, const void* src) {
    uint32_t d = (uint32_t)__cvta_generic_to_shared(dst);
    asm volatile("cp.async.ca.shared.global [%0], [%1], 16;" :: "r"(d), "l"(src));
}
__device__ __forceinline__ void cpa_commit() { asm volatile("cp.async.commit_group;"); }
__device__ __forceinline__ void cpa_wait1() { asm volatile("cp.async.wait_group 1;"); }
__device__ __forceinline__ void cpa_wait0() { asm volatile("cp.async.wait_group 0;"); }

// =======================================================================
// kernel 1: QKV projections, fp16 MMA, reg-prefetch pipeline.
// Block 128x128, BK=16, 8 warps 2x4. V is stored TRANSPOSED [b,h,d,n].
// =======================================================================
__global__ void __launch_bounds__(256, 2)
proj_f16(const float* __restrict__ x, const float* __restrict__ Wq,
         const float* __restrict__ Wk, const float* __restrict__ Wv) {
    __shared__ uint32_t Ah2[8][132], Bh2[8][132];
    int which = blockIdx.z;
    const float* W = which == 0 ? Wq : (which == 1 ? Wk : Wv);
    __half* dst = which == 0 ? g_q : (which == 1 ? g_k : g_v);
    float scale = (which == 1) ? 0.125f : 1.0f;

    int tid = threadIdx.x, lane = tid & 31, w = tid >> 5;
    int wm = (w & 1) * 64, wn = (w >> 1) * 32;
    int row0 = blockIdx.y * 128, col0 = blockIdx.x * 128;

    int am0 = tid >> 2, ak0 = (tid & 3) * 4;
    int am1 = (tid + 256) >> 2, ak1 = ((tid + 256) & 3) * 4;
    int bkp = tid >> 5, bn4 = (tid & 31) * 4;

    float4 ra0, ra1, rb0, rb1;
    ra0 = *(const float4*)&x[(size_t)(row0 + am0) * Dc + ak0];
    ra1 = *(const float4*)&x[(size_t)(row0 + am1) * Dc + ak1];
    rb0 = *(const float4*)&W[(size_t)(2 * bkp) * (Hc * HDc) + col0 + bn4];
    rb1 = *(const float4*)&W[(size_t)(2 * bkp + 1) * (Hc * HDc) + col0 + bn4];

    float acc[4][4][4];
#pragma unroll
    for (int a = 0; a < 4; a++)
#pragma unroll
        for (int b = 0; b < 4; b++)
#pragma unroll
            for (int c = 0; c < 4; c++) acc[a][b][c] = 0.f;

    for (int kt = 0; kt < Dc; kt += 16) {
        Ah2[ak0 >> 1][am0] = pack2(ra0.x, ra0.y);
        Ah2[(ak0 >> 1) + 1][am0] = pack2(ra0.z, ra0.w);
        Ah2[ak1 >> 1][am1] = pack2(ra1.x, ra1.y);
        Ah2[(ak1 >> 1) + 1][am1] = pack2(ra1.z, ra1.w);
        uint4 st = {pack2(rb0.x, rb1.x), pack2(rb0.y, rb1.y), pack2(rb0.z, rb1.z), pack2(rb0.w, rb1.w)};
        *(uint4*)&Bh2[bkp][bn4] = st;
        __syncthreads();
        if (kt + 16 < Dc) {
            ra0 = *(const float4*)&x[(size_t)(row0 + am0) * Dc + kt + 16 + ak0];
            ra1 = *(const float4*)&x[(size_t)(row0 + am1) * Dc + kt + 16 + ak1];
            rb0 = *(const float4*)&W[(size_t)(kt + 16 + 2 * bkp) * (Hc * HDc) + col0 + bn4];
            rb1 = *(const float4*)&W[(size_t)(kt + 16 + 2 * bkp + 1) * (Hc * HDc) + col0 + bn4];
        }
        int kr = lane & 3, rr = lane >> 2;
        uint32_t ah[4][4], bh[4][2];
#pragma unroll
        for (int mi = 0; mi < 4; mi++) {
            int rb = wm + mi * 16 + rr;
            ah[mi][0] = Ah2[kr][rb];
            ah[mi][1] = Ah2[kr][rb + 8];
            ah[mi][2] = Ah2[kr + 4][rb];
            ah[mi][3] = Ah2[kr + 4][rb + 8];
        }
#pragma unroll
        for (int ni = 0; ni < 4; ni++) {
            int nb = wn + ni * 8 + rr;
            bh[ni][0] = Bh2[kr][nb];
            bh[ni][1] = Bh2[kr + 4][nb];
        }
#pragma unroll
        for (int mi = 0; mi < 4; mi++)
#pragma unroll
            for (int ni = 0; ni < 4; ni++) {
                float* c = acc[mi][ni];
                mma16(c[0], c[1], c[2], c[3], ah[mi][0], ah[mi][1], ah[mi][2], ah[mi][3], bh[ni][0], bh[ni][1]);
            }
        __syncthreads();
    }
#pragma unroll
    for (int mi = 0; mi < 4; mi++) {
        int r0 = row0 + wm + mi * 16 + (lane >> 2);
        int r1 = r0 + 8;
        int b0i = r0 >> 11, n0i = r0 & (Nc - 1);
        int b1i = r1 >> 11, n1i = r1 & (Nc - 1);
#pragma unroll
        for (int ni = 0; ni < 4; ni++) {
            int c = col0 + wn + ni * 8 + (lane & 3) * 2;
            int h = c >> 6, d = c & 63;
            if (which == 2) {
                // transposed store: Vt[b,h,d,n]
                size_t base0 = (size_t)(b0i * Hc + h) * HDc;
                size_t base1 = (size_t)(b1i * Hc + h) * HDc;
                dst[(base0 + d) * Nc + n0i]     = __float2half_rn(acc[mi][ni][0]);
                dst[(base0 + d + 1) * Nc + n0i] = __float2half_rn(acc[mi][ni][1]);
                dst[(base1 + d) * Nc + n1i]     = __float2half_rn(acc[mi][ni][2]);
                dst[(base1 + d + 1) * Nc + n1i] = __float2half_rn(acc[mi][ni][3]);
            } else {
                __half2 v0 = __floats2half2_rn(acc[mi][ni][0] * scale, acc[mi][ni][1] * scale);
                __half2 v1 = __floats2half2_rn(acc[mi][ni][2] * scale, acc[mi][ni][3] * scale);
                *(__half2*)&dst[(((size_t)b0i * Hc + h) * Nc + n0i) * HDc + d] = v0;
                *(__half2*)&dst[(((size_t)b1i * Hc + h) * Nc + n1i) * HDc + d] = v1;
            }
        }
    }
}

// =======================================================================
// kernel 2: S = Q K^T per (b,h), fp16 MMA, reg-prefetch. Block 128x128, K=64.
// =======================================================================
__global__ void __launch_bounds__(256, 2) scores_f16() {
    __shared__ uint32_t Ah2[8][132], Bh2[8][132];
    int bh_ = blockIdx.z;
    const __half* Q = g_q + (size_t)bh_ * Nc * HDc;
    const __half* Kc = g_k + (size_t)bh_ * Nc * HDc;

    int tid = threadIdx.x, lane = tid & 31, w = tid >> 5;
    int wm = (w & 1) * 64, wn = (w >> 1) * 32;
    int row0 = blockIdx.y * 128, col0 = blockIdx.x * 128;

    int lm = tid >> 1, lko = (tid & 1) * 8;

    uint4 rqa, rkb;
    rqa = *(const uint4*)&Q[(size_t)(row0 + lm) * HDc + lko];
    rkb = *(const uint4*)&Kc[(size_t)(col0 + lm) * HDc + lko];

    float acc[4][4][4];
#pragma unroll
    for (int a = 0; a < 4; a++)
#pragma unroll
        for (int b = 0; b < 4; b++)
#pragma unroll
            for (int c = 0; c < 4; c++) acc[a][b][c] = 0.f;

    for (int kt = 0; kt < HDc; kt += 16) {
        Ah2[(lko >> 1) + 0][lm] = rqa.x;
        Ah2[(lko >> 1) + 1][lm] = rqa.y;
        Ah2[(lko >> 1) + 2][lm] = rqa.z;
        Ah2[(lko >> 1) + 3][lm] = rqa.w;
        Bh2[(lko >> 1) + 0][lm] = rkb.x;
        Bh2[(lko >> 1) + 1][lm] = rkb.y;
        Bh2[(lko >> 1) + 2][lm] = rkb.z;
        Bh2[(lko >> 1) + 3][lm] = rkb.w;
        __syncthreads();
        if (kt + 16 < HDc) {
            rqa = *(const uint4*)&Q[(size_t)(row0 + lm) * HDc + kt + 16 + lko];
            rkb = *(const uint4*)&Kc[(size_t)(col0 + lm) * HDc + kt + 16 + lko];
        }
        int kr = lane & 3, rr = lane >> 2;
        uint32_t ah[4][4], bh[4][2];
#pragma unroll
        for (int mi = 0; mi < 4; mi++) {
            int rb = wm + mi * 16 + rr;
            ah[mi][0] = Ah2[kr][rb];
            ah[mi][1] = Ah2[kr][rb + 8];
            ah[mi][2] = Ah2[kr + 4][rb];
            ah[mi][3] = Ah2[kr + 4][rb + 8];
        }
#pragma unroll
        for (int ni = 0; ni < 4; ni++) {
            int nb = wn + ni * 8 + rr;
            bh[ni][0] = Bh2[kr][nb];
            bh[ni][1] = Bh2[kr + 4][nb];
        }
#pragma unroll
        for (int mi = 0; mi < 4; mi++)
#pragma unroll
            for (int ni = 0; ni < 4; ni++) {
                float* c = acc[mi][ni];
                mma16(c[0], c[1], c[2], c[3], ah[mi][0], ah[mi][1], ah[mi][2], ah[mi][3], bh[ni][0], bh[ni][1]);
            }
        __syncthreads();
    }
    size_t base = (size_t)bh_ * Nc * Nc;
#pragma unroll
    for (int mi = 0; mi < 4; mi++) {
        int r0 = row0 + wm + mi * 16 + (lane >> 2);
        int r1 = r0 + 8;
#pragma unroll
        for (int ni = 0; ni < 4; ni++) {
            int c = col0 + wn + ni * 8 + (lane & 3) * 2;
            *(__half2*)&g_s[base + (size_t)r0 * Nc + c] = __floats2half2_rn(acc[mi][ni][0], acc[mi][ni][1]);
            *(__half2*)&g_s[base + (size_t)r1 * Nc + c] = __floats2half2_rn(acc[mi][ni][2], acc[mi][ni][3]);
        }
    }
}

// ---------------- fast exp on FMA pipe ----------------
__device__ __forceinline__ float exp_fast(float x) {
    float y = fmaxf(x * 1.4426950408889634f, -125.0f);
    float r = y + 12582912.0f;
    int ir = __float_as_int(r) - 0x4B400000;
    float rf = r - 12582912.0f;
    float f = y - rf;
    float p = 1.5403530e-4f;
    p = fmaf(p, f, 1.3333558e-3f);
    p = fmaf(p, f, 9.6181291e-3f);
    p = fmaf(p, f, 5.5504109e-2f);
    p = fmaf(p, f, 2.4022651e-1f);
    p = fmaf(p, f, 6.9314718e-1f);
    p = fmaf(p, f, 1.0f);
    return p * __int_as_float((ir + 127) << 23);
}

// ---------------- kernel 3: L-mix -> exp -> Wm-mix, 2-pass, 256 threads ----------------
__global__ void __launch_bounds__(256)
talk_kernel(const float* __restrict__ Lm, const float* __restrict__ Wmm) {
    extern __shared__ float s[];                 // [16][2048] fp32
    __shared__ float sL[256], sWp[256];
    __shared__ float red[16 * 8];
    __shared__ float ginv[16];

    int tid = threadIdx.x;
    int lane = tid & 31, wid = tid >> 5;
    int bn = blockIdx.x;
    int b = bn >> 11, n = bn & (Nc - 1);
    const size_t HSTRIDE = (size_t)Nc * Nc;
    size_t base = ((size_t)b * Hc) * HSTRIDE + (size_t)n * Nc;

    sL[tid] = Lm[tid];
    for (int idx = tid; idx < Hc * (Nc / 8); idx += 256) {
        int h = idx >> 8, c8 = (idx & 255) * 8;
        uint4 u = *(const uint4*)&g_s[base + (size_t)h * HSTRIDE + c8];
        float2 f0 = __half22float2(*(__half2*)&u.x);
        float2 f1 = __half22float2(*(__half2*)&u.y);
        float2 f2 = __half22float2(*(__half2*)&u.z);
        float2 f3 = __half22float2(*(__half2*)&u.w);
        float4* d = (float4*)&s[h * Nc + c8];
        d[0] = make_float4(f0.x, f0.y, f1.x, f1.y);
        d[1] = make_float4(f2.x, f2.y, f3.x, f3.y);
    }
    __syncthreads();

    float lsum[16];
#pragma unroll
    for (int g = 0; g < 16; g++) lsum[g] = 0.f;
    for (int j = 0; j < Nc / 256; j++) {
        int m = tid + j * 256;
        float sv[16], pv[16];
#pragma unroll
        for (int h = 0; h < 16; h++) sv[h] = s[h * Nc + m];
#pragma unroll
        for (int g = 0; g < 16; g++) {
            float t = -8.0f;
#pragma unroll
            for (int h = 0; h < 16; h++) t = fmaf(sL[g * 16 + h], sv[h], t);
            float p = exp_fast(t);
            lsum[g] += p;
            pv[g] = p;
        }
#pragma unroll
        for (int g = 0; g < 16; g++) s[g * Nc + m] = pv[g];
    }
#pragma unroll
    for (int g = 0; g < 16; g++) {
        float v = lsum[g];
        for (int o = 16; o; o >>= 1) v += __shfl_xor_sync(0xFFFFFFFFu, v, o);
        if (lane == 0) red[g * 8 + wid] = v;
    }
    __syncthreads();
    if (tid < 16) {
        float v = 0.f;
#pragma unroll
        for (int w = 0; w < 8; w++) v += red[tid * 8 + w];
        ginv[tid] = 1.0f / v;
    }
    __syncthreads();
    sWp[tid] = Wmm[tid] * ginv[tid & 15];
    __syncthreads();

    for (int j = 0; j < Nc / 256; j++) {
        int m = tid + j * 256;
        float pv[16];
#pragma unroll
        for (int g = 0; g < 16; g++) pv[g] = s[g * Nc + m];
#pragma unroll
        for (int g2 = 0; g2 < 16; g2++) {
            float u = 0.f;
#pragma unroll
            for (int g = 0; g < 16; g++) u = fmaf(sWp[g2 * 16 + g], pv[g], u);
            g_s[base + (size_t)g2 * HSTRIDE + m] = __float2half_rn(u);
        }
    }
}

// =======================================================================
// kernel 4: O = attn @ V per (b,g). cp.async 2-stage pipeline, BK=64.
// 128(n) x 64(d) tile, K=2048, 32 iterations, 8 warps as 4(m32)x2(n32).
// V is transposed [d][n] so B k-pairs are memory-contiguous.
// smem: A[2][128][36w], B[2][64][36w] (36-word stride = conflict-free LDS).
// =======================================================================
#define AV_AROW 36
#define AV_ASTG (128 * AV_AROW)
#define AV_BSTG (64 * AV_AROW)
__global__ void __launch_bounds__(256) av_f16() {
    extern __shared__ uint32_t sm[];
    uint32_t* Am = sm;                   // 2 stages of A
    uint32_t* Bm = sm + 2 * AV_ASTG;     // 2 stages of B
    int bh_ = blockIdx.y;
    const __half* U = g_s + (size_t)bh_ * Nc * Nc;
    const __half* Vt = g_v + (size_t)bh_ * Nc * HDc;  // [d][m]

    int tid = threadIdx.x, lane = tid & 31, w = tid >> 5;
    int wm = (w >> 1) * 32, wn = (w & 1) * 32;
    int row0 = blockIdx.x * 128;

    float acc[2][4][4];
#pragma unroll
    for (int a = 0; a < 2; a++)
#pragma unroll
        for (int b = 0; b < 4; b++)
#pragma unroll
            for (int c = 0; c < 4; c++) acc[a][b][c] = 0.f;

    // stage loader: A = 128 rows x 128B (1024 x16B), B = 64 rows x 128B (512 x16B)
    auto load_stage = [&](int s, int kt) {
#pragma unroll
        for (int c = 0; c < 4; c++) {
            int idx = tid + c * 256;
            int m = idx >> 3, ch = idx & 7;
            cpa16(&Am[s * AV_ASTG + m * AV_AROW + ch * 4],
                  &U[(size_t)(row0 + m) * Nc + kt + ch * 8]);
        }
#pragma unroll
        for (int c = 0; c < 2; c++) {
            int idx = tid + c * 256;
            int d = idx >> 3, ch = idx & 7;
            cpa16(&Bm[s * AV_BSTG + d * AV_AROW + ch * 4],
                  &Vt[(size_t)d * Nc + kt + ch * 8]);
        }
        cpa_commit();
    };

    load_stage(0, 0);
    const int NI = Nc / 64;  // 32
    for (int i = 0; i < NI; i++) {
        int s = i & 1;
        if (i + 1 < NI) {
            load_stage(s ^ 1, (i + 1) * 64);
            cpa_wait1();
        } else {
            cpa_wait0();
        }
        __syncthreads();
        int kr = lane & 3, rr = lane >> 2;
        const uint32_t* As = Am + s * AV_ASTG;
        const uint32_t* Bs = Bm + s * AV_BSTG;
#pragma unroll
        for (int kk = 0; kk < 4; kk++) {
            int kpb = kk * 8;
            uint32_t ah[2][4], bh[4][2];
#pragma unroll
            for (int mi = 0; mi < 2; mi++) {
                int rb = wm + mi * 16 + rr;
                ah[mi][0] = As[rb * AV_AROW + kpb + kr];
                ah[mi][1] = As[(rb + 8) * AV_AROW + kpb + kr];
                ah[mi][2] = As[rb * AV_AROW + kpb + kr + 4];
                ah[mi][3] = As[(rb + 8) * AV_AROW + kpb + kr + 4];
            }
#pragma unroll
            for (int ni = 0; ni < 4; ni++) {
                int dn = wn + ni * 8 + rr;
                bh[ni][0] = Bs[dn * AV_AROW + kpb + kr];
                bh[ni][1] = Bs[dn * AV_AROW + kpb + kr + 4];
            }
#pragma unroll
            for (int mi = 0; mi < 2; mi++)
#pragma unroll
                for (int ni = 0; ni < 4; ni++) {
                    float* c = acc[mi][ni];
                    mma16(c[0], c[1], c[2], c[3], ah[mi][0], ah[mi][1], ah[mi][2], ah[mi][3], bh[ni][0], bh[ni][1]);
                }
        }
        __syncthreads();
    }
    int b = bh_ >> 4, g = bh_ & 15;
#pragma unroll
    for (int mi = 0; mi < 2; mi++) {
        int r0 = row0 + wm + mi * 16 + (lane >> 2);
        int r1 = r0 + 8;
#pragma unroll
        for (int ni = 0; ni < 4; ni++) {
            int d = wn + ni * 8 + (lane & 3) * 2;
            *(__half2*)&g_o[((size_t)b * Nc + r0) * (Hc * HDc) + g * HDc + d] =
                __floats2half2_rn(acc[mi][ni][0], acc[mi][ni][1]);
            *(__half2*)&g_o[((size_t)b * Nc + r1) * (Hc * HDc) + g * HDc + d] =
                __floats2half2_rn(acc[mi][ni][2], acc[mi][ni][3]);
        }
    }
}
#define AV_SMEM ((2 * AV_ASTG + 2 * AV_BSTG) * 4)

// =======================================================================
// kernel 5: out = g_o @ Wo + bo, fp16 MMA, reg-prefetch. 128x128, K=1024.
// =======================================================================
__global__ void __launch_bounds__(256, 2)
out_f16(const float* __restrict__ Wo, const float* __restrict__ bo,
        float* __restrict__ out) {
    __shared__ uint32_t Ah2[8][132], Bh2[8][132];
    int tid = threadIdx.x, lane = tid & 31, w = tid >> 5;
    int wm = (w & 1) * 64, wn = (w >> 1) * 32;
    int row0 = blockIdx.y * 128, col0 = blockIdx.x * 128;

    int lm = tid >> 1, lko = (tid & 1) * 8;
    int bkp = tid >> 5, bn4 = (tid & 31) * 4;

    uint4 roa;
    float4 rb0, rb1;
    roa = *(const uint4*)&g_o[(size_t)(row0 + lm) * (Hc * HDc) + lko];
    rb0 = *(const float4*)&Wo[(size_t)(2 * bkp) * Dc + col0 + bn4];
    rb1 = *(const float4*)&Wo[(size_t)(2 * bkp + 1) * Dc + col0 + bn4];

    float acc[4][4][4];
#pragma unroll
    for (int a = 0; a < 4; a++)
#pragma unroll
        for (int b = 0; b < 4; b++)
#pragma unroll
            for (int c = 0; c < 4; c++) acc[a][b][c] = 0.f;

    for (int kt = 0; kt < Hc * HDc; kt += 16) {
        Ah2[(lko >> 1) + 0][lm] = roa.x;
        Ah2[(lko >> 1) + 1][lm] = roa.y;
        Ah2[(lko >> 1) + 2][lm] = roa.z;
        Ah2[(lko >> 1) + 3][lm] = roa.w;
        uint4 st = {pack2(rb0.x, rb1.x), pack2(rb0.y, rb1.y), pack2(rb0.z, rb1.z), pack2(rb0.w, rb1.w)};
        *(uint4*)&Bh2[bkp][bn4] = st;
        __syncthreads();
        if (kt + 16 < Hc * HDc) {
            roa = *(const uint4*)&g_o[(size_t)(row0 + lm) * (Hc * HDc) + kt + 16 + lko];
            rb0 = *(const float4*)&Wo[(size_t)(kt + 16 + 2 * bkp) * Dc + col0 + bn4];
            rb1 = *(const float4*)&Wo[(size_t)(kt + 16 + 2 * bkp + 1) * Dc + col0 + bn4];
        }
        int kr = lane & 3, rr = lane >> 2;
        uint32_t ah[4][4], bh[4][2];
#pragma unroll
        for (int mi = 0; mi < 4; mi++) {
            int rb = wm + mi * 16 + rr;
            ah[mi][0] = Ah2[kr][rb];
            ah[mi][1] = Ah2[kr][rb + 8];
            ah[mi][2] = Ah2[kr + 4][rb];
            ah[mi][3] = Ah2[kr + 4][rb + 8];
        }
#pragma unroll
        for (int ni = 0; ni < 4; ni++) {
            int nb = wn + ni * 8 + rr;
            bh[ni][0] = Bh2[kr][nb];
            bh[ni][1] = Bh2[kr + 4][nb];
        }
#pragma unroll
        for (int mi = 0; mi < 4; mi++)
#pragma unroll
            for (int ni = 0; ni < 4; ni++) {
                float* c = acc[mi][ni];
                mma16(c[0], c[1], c[2], c[3], ah[mi][0], ah[mi][1], ah[mi][2], ah[mi][3], bh[ni][0], bh[ni][1]);
            }
        __syncthreads();
    }
#pragma unroll
    for (int mi = 0; mi < 4; mi++) {
        int r0 = row0 + wm + mi * 16 + (lane >> 2);
        int r1 = r0 + 8;
#pragma unroll
        for (int ni = 0; ni < 4; ni++) {
            int c = col0 + wn + ni * 8 + (lane & 3) * 2;
            float2 bias = {bo[c], bo[c + 1]};
            float2 v0 = {acc[mi][ni][0] + bias.x, acc[mi][ni][1] + bias.y};
            float2 v1 = {acc[mi][ni][2] + bias.x, acc[mi][ni][3] + bias.y};
            *(float2*)&out[(size_t)r0 * Dc + c] = v0;
            *(float2*)&out[(size_t)r1 * Dc + c] = v1;
        }
    }
}

// ---------------- launch ----------------
extern "C" void kernel_launch(void* const* d_in, const int* in_sizes, int n_in,
                              void* d_out, int out_size) {
    const float* x  = (const float*)d_in[0];
    const float* Wq = (const float*)d_in[1];
    const float* Wk = (const float*)d_in[2];
    const float* Wv = (const float*)d_in[3];
    const float* L  = (const float*)d_in[4];
    const float* Wm = (const float*)d_in[5];
    const float* Wo = (const float*)d_in[6];
    const float* bo = (const float*)d_in[7];
    float* out = (float*)d_out;
    (void)in_sizes; (void)n_in; (void)out_size;

    proj_f16<<<dim3((Hc * HDc) / 128, (Bc * Nc) / 128, 3), 256>>>(x, Wq, Wk, Wv);

    scores_f16<<<dim3(Nc / 128, Nc / 128, Bc * Hc), 256>>>();

    const int TALK_SMEM = Hc * Nc * sizeof(float);  // 128KB
    (void)cudaFuncSetAttribute(talk_kernel, cudaFuncAttributeMaxDynamicSharedMemorySize, TALK_SMEM);
    talk_kernel<<<Bc * Nc, 256, TALK_SMEM>>>(L, Wm);

    (void)cudaFuncSetAttribute(av_f16, cudaFuncAttributeMaxDynamicSharedMemorySize, AV_SMEM);
    av_f16<<<dim3(Nc / 128, Bc * Hc), 256, AV_SMEM>>>();

    out_f16<<<dim3(Dc / 128, (Bc * Nc) / 128), 256>>>(Wo, bo, out);
}

// round 13
// speedup vs baseline: 2.2697x; 1.1064x over previous
#include <cuda_runtime.h>
#include <cuda_fp16.h>
#include <cstdint>

// B=2, N=2048, D=1024, H=16, HD=64
#define Bc 2
#define Nc 2048
#define Dc 1024
#define Hc 16
#define HDc 64

// ---------------- scratch ----------------
__device__ __half g_x16[(size_t)Bc * Nc * Dc];       // x in fp16
__device__ __half g_wq16[(size_t)Dc * Dc];           // W^T fp16 [n][k]
__device__ __half g_wk16[(size_t)Dc * Dc];           // pre-scaled 0.125
__device__ __half g_wv16[(size_t)Dc * Dc];
__device__ __half g_wo16[(size_t)Dc * Dc];
__device__ __half g_q[(size_t)Bc * Hc * Nc * HDc];
__device__ __half g_k[(size_t)Bc * Hc * Nc * HDc];
__device__ __half g_v[(size_t)Bc * Hc * Nc * HDc];   // TRANSPOSED: [b,h,d,n]
__device__ __half g_s[(size_t)Bc * Hc * Nc * Nc];    // 268MB, in-place
__device__ __half g_o[(size_t)Bc * Nc * Hc * HDc];

// ---------------- helpers ----------------
__device__ __forceinline__ void mma16(float& c0, float& c1, float& c2, float& c3,
                                      uint32_t a0, uint32_t a1, uint32_t a2, uint32_t a3,
                                      uint32_t b0, uint32_t b1) {
    asm volatile(
        "mma.sync.aligned.m16n8k16.row.col.f32.f16.f16.f32 "
        "{%0,%1,%2,%3}, {%4,%5,%6,%7}, {%8,%9}, {%0,%1,%2,%3};"
        : "+f"(c0), "+f"(c1), "+f"(c2), "+f"(c3)
        : "r"(a0), "r"(a1), "r"(a2), "r"(a3), "r"(b0), "r"(b1));
}
__device__ __forceinline__ void cpa16(void* dst, const void* src) {
    uint32_t d = (uint32_t)__cvta_generic_to_shared(dst);
    asm volatile("cp.async.ca.shared.global [%0], [%1], 16;" :: "r"(d), "l"(src));
}
__device__ __forceinline__ void cpa_commit() { asm volatile("cp.async.commit_group;"); }
__device__ __forceinline__ void cpa_wait1() { asm volatile("cp.async.wait_group 1;"); }
__device__ __forceinline__ void cpa_wait0() { asm volatile("cp.async.wait_group 0;"); }

#define ROWW 36   // smem row stride in words (32 data + 4 pad): conflict-free

// =======================================================================
// kernel 0a: x -> fp16
// =======================================================================
__global__ void __launch_bounds__(256) xconv(const float* __restrict__ x) {
    size_t i = (size_t)blockIdx.x * 256 + threadIdx.x;
    float4 v = ((const float4*)x)[i];
    ((__half2*)g_x16)[2 * i]     = __floats2half2_rn(v.x, v.y);
    ((__half2*)g_x16)[2 * i + 1] = __floats2half2_rn(v.z, v.w);
}

// =======================================================================
// kernel 0b: weights -> fp16 transposed [n][k]; Wk gets 0.125 (exact pow2)
// =======================================================================
__global__ void __launch_bounds__(256) wconv(const float* __restrict__ Wq,
                                             const float* __restrict__ Wk,
                                             const float* __restrict__ Wv,
                                             const float* __restrict__ Wo) {
    __shared__ float t[32][33];
    int which = blockIdx.z;
    const float* src = which == 0 ? Wq : (which == 1 ? Wk : (which == 2 ? Wv : Wo));
    __half* dst = which == 0 ? g_wq16 : (which == 1 ? g_wk16 : (which == 2 ? g_wv16 : g_wo16));
    float sc = (which == 1) ? 0.125f : 1.0f;
    int k0 = blockIdx.y * 32, n0 = blockIdx.x * 32;
    int tx = threadIdx.x & 31, tg = threadIdx.x >> 5;   // 32 x 8
#pragma unroll
    for (int i = 0; i < 4; i++) {
        int ty = tg * 4 + i;
        t[ty][tx] = src[(size_t)(k0 + ty) * Dc + n0 + tx];
    }
    __syncthreads();
#pragma unroll
    for (int i = 0; i < 4; i++) {
        int ty = tg * 4 + i;
        dst[(size_t)(n0 + ty) * Dc + k0 + tx] = __float2half_rn(t[tx][ty] * sc);
    }
}

// =======================================================================
// kernel 1: QKV projections. cp.async 2-stage BK=64 pipeline, all fp16.
// Block 128(m) x 128(n), K=1024 -> 16 iters. 8 warps 2(m64) x 4(n32).
// V stored transposed [b,h,d,n].
// =======================================================================
#define P_STG (128 * ROWW)
__global__ void __launch_bounds__(256) proj_f16() {
    extern __shared__ uint32_t sm[];
    uint32_t* Am = sm;
    uint32_t* Bm = sm + 2 * P_STG;
    int which = blockIdx.z;
    const __half* Wt = which == 0 ? g_wq16 : (which == 1 ? g_wk16 : g_wv16);
    __half* dst = which == 0 ? g_q : (which == 1 ? g_k : g_v);

    int tid = threadIdx.x, lane = tid & 31, w = tid >> 5;
    int wm = (w & 1) * 64, wn = (w >> 1) * 32;
    int row0 = blockIdx.y * 128, col0 = blockIdx.x * 128;

    float acc[4][4][4];
#pragma unroll
    for (int a = 0; a < 4; a++)
#pragma unroll
        for (int b = 0; b < 4; b++)
#pragma unroll
            for (int c = 0; c < 4; c++) acc[a][b][c] = 0.f;

    auto load_stage = [&](int s, int kt) {
#pragma unroll
        for (int c = 0; c < 4; c++) {
            int idx = tid + c * 256;
            int m = idx >> 3, ch = idx & 7;
            cpa16(&Am[s * P_STG + m * ROWW + ch * 4],
                  &g_x16[(size_t)(row0 + m) * Dc + kt + ch * 8]);
        }
#pragma unroll
        for (int c = 0; c < 4; c++) {
            int idx = tid + c * 256;
            int n = idx >> 3, ch = idx & 7;
            cpa16(&Bm[s * P_STG + n * ROWW + ch * 4],
                  &Wt[(size_t)(col0 + n) * Dc + kt + ch * 8]);
        }
        cpa_commit();
    };

    load_stage(0, 0);
    const int NI = Dc / 64;  // 16
    for (int i = 0; i < NI; i++) {
        int s = i & 1;
        if (i + 1 < NI) { load_stage(s ^ 1, (i + 1) * 64); cpa_wait1(); }
        else cpa_wait0();
        __syncthreads();
        int kr = lane & 3, rr = lane >> 2;
        const uint32_t* As = Am + s * P_STG;
        const uint32_t* Bs = Bm + s * P_STG;
#pragma unroll
        for (int kk = 0; kk < 4; kk++) {
            int kpb = kk * 8;
            uint32_t ah[4][4], bh[4][2];
#pragma unroll
            for (int mi = 0; mi < 4; mi++) {
                int rb = wm + mi * 16 + rr;
                ah[mi][0] = As[rb * ROWW + kpb + kr];
                ah[mi][1] = As[(rb + 8) * ROWW + kpb + kr];
                ah[mi][2] = As[rb * ROWW + kpb + kr + 4];
                ah[mi][3] = As[(rb + 8) * ROWW + kpb + kr + 4];
            }
#pragma unroll
            for (int ni = 0; ni < 4; ni++) {
                int nb = wn + ni * 8 + rr;
                bh[ni][0] = Bs[nb * ROWW + kpb + kr];
                bh[ni][1] = Bs[nb * ROWW + kpb + kr + 4];
            }
#pragma unroll
            for (int mi = 0; mi < 4; mi++)
#pragma unroll
                for (int ni = 0; ni < 4; ni++) {
                    float* c = acc[mi][ni];
                    mma16(c[0], c[1], c[2], c[3], ah[mi][0], ah[mi][1], ah[mi][2], ah[mi][3], bh[ni][0], bh[ni][1]);
                }
        }
        __syncthreads();
    }
#pragma unroll
    for (int mi = 0; mi < 4; mi++) {
        int r0 = row0 + wm + mi * 16 + (lane >> 2);
        int r1 = r0 + 8;
        int b0i = r0 >> 11, n0i = r0 & (Nc - 1);
        int b1i = r1 >> 11, n1i = r1 & (Nc - 1);
#pragma unroll
        for (int ni = 0; ni < 4; ni++) {
            int c = col0 + wn + ni * 8 + (lane & 3) * 2;
            int h = c >> 6, d = c & 63;
            if (which == 2) {
                size_t base0 = (size_t)(b0i * Hc + h) * HDc;
                size_t base1 = (size_t)(b1i * Hc + h) * HDc;
                dst[(base0 + d) * Nc + n0i]     = __float2half_rn(acc[mi][ni][0]);
                dst[(base0 + d + 1) * Nc + n0i] = __float2half_rn(acc[mi][ni][1]);
                dst[(base1 + d) * Nc + n1i]     = __float2half_rn(acc[mi][ni][2]);
                dst[(base1 + d + 1) * Nc + n1i] = __float2half_rn(acc[mi][ni][3]);
            } else {
                *(__half2*)&dst[(((size_t)b0i * Hc + h) * Nc + n0i) * HDc + d] =
                    __floats2half2_rn(acc[mi][ni][0], acc[mi][ni][1]);
                *(__half2*)&dst[(((size_t)b1i * Hc + h) * Nc + n1i) * HDc + d] =
                    __floats2half2_rn(acc[mi][ni][2], acc[mi][ni][3]);
            }
        }
    }
}
#define P_SMEM (4 * P_STG * 4)

// =======================================================================
// kernel 2: S = Q K^T per (b,h). Single-stage cp.async, K=64 (one barrier).
// Block 128(n) x 128(m). 8 warps 2x4.
// =======================================================================
__global__ void __launch_bounds__(256) scores_f16() {
    __shared__ uint32_t As[128 * ROWW], Bs[128 * ROWW];
    int bh_ = blockIdx.z;
    const __half* Q = g_q + (size_t)bh_ * Nc * HDc;
    const __half* Kc = g_k + (size_t)bh_ * Nc * HDc;

    int tid = threadIdx.x, lane = tid & 31, w = tid >> 5;
    int wm = (w & 1) * 64, wn = (w >> 1) * 32;
    int row0 = blockIdx.y * 128, col0 = blockIdx.x * 128;

#pragma unroll
    for (int c = 0; c < 4; c++) {
        int idx = tid + c * 256;
        int m = idx >> 3, ch = idx & 7;
        cpa16(&As[m * ROWW + ch * 4], &Q[(size_t)(row0 + m) * HDc + ch * 8]);
    }
#pragma unroll
    for (int c = 0; c < 4; c++) {
        int idx = tid + c * 256;
        int n = idx >> 3, ch = idx & 7;
        cpa16(&Bs[n * ROWW + ch * 4], &Kc[(size_t)(col0 + n) * HDc + ch * 8]);
    }
    cpa_commit();
    cpa_wait0();
    __syncthreads();

    float acc[4][4][4];
#pragma unroll
    for (int a = 0; a < 4; a++)
#pragma unroll
        for (int b = 0; b < 4; b++)
#pragma unroll
            for (int c = 0; c < 4; c++) acc[a][b][c] = 0.f;

    int kr = lane & 3, rr = lane >> 2;
#pragma unroll
    for (int kk = 0; kk < 4; kk++) {
        int kpb = kk * 8;
        uint32_t ah[4][4], bh[4][2];
#pragma unroll
        for (int mi = 0; mi < 4; mi++) {
            int rb = wm + mi * 16 + rr;
            ah[mi][0] = As[rb * ROWW + kpb + kr];
            ah[mi][1] = As[(rb + 8) * ROWW + kpb + kr];
            ah[mi][2] = As[rb * ROWW + kpb + kr + 4];
            ah[mi][3] = As[(rb + 8) * ROWW + kpb + kr + 4];
        }
#pragma unroll
        for (int ni = 0; ni < 4; ni++) {
            int nb = wn + ni * 8 + rr;
            bh[ni][0] = Bs[nb * ROWW + kpb + kr];
            bh[ni][1] = Bs[nb * ROWW + kpb + kr + 4];
        }
#pragma unroll
        for (int mi = 0; mi < 4; mi++)
#pragma unroll
            for (int ni = 0; ni < 4; ni++) {
                float* c = acc[mi][ni];
                mma16(c[0], c[1], c[2], c[3], ah[mi][0], ah[mi][1], ah[mi][2], ah[mi][3], bh[ni][0], bh[ni][1]);
            }
    }
    size_t base = (size_t)bh_ * Nc * Nc;
#pragma unroll
    for (int mi = 0; mi < 4; mi++) {
        int r0 = row0 + wm + mi * 16 + (lane >> 2);
        int r1 = r0 + 8;
#pragma unroll
        for (int ni = 0; ni < 4; ni++) {
            int c = col0 + wn + ni * 8 + (lane & 3) * 2;
            *(__half2*)&g_s[base + (size_t)r0 * Nc + c] = __floats2half2_rn(acc[mi][ni][0], acc[mi][ni][1]);
            *(__half2*)&g_s[base + (size_t)r1 * Nc + c] = __floats2half2_rn(acc[mi][ni][2], acc[mi][ni][3]);
        }
    }
}

// ---------------- fast exp on FMA pipe ----------------
__device__ __forceinline__ float exp_fast(float x) {
    float y = fmaxf(x * 1.4426950408889634f, -125.0f);
    float r = y + 12582912.0f;
    int ir = __float_as_int(r) - 0x4B400000;
    float rf = r - 12582912.0f;
    float f = y - rf;
    float p = 1.5403530e-4f;
    p = fmaf(p, f, 1.3333558e-3f);
    p = fmaf(p, f, 9.6181291e-3f);
    p = fmaf(p, f, 5.5504109e-2f);
    p = fmaf(p, f, 2.4022651e-1f);
    p = fmaf(p, f, 6.9314718e-1f);
    p = fmaf(p, f, 1.0f);
    return p * __int_as_float((ir + 127) << 23);
}

// ---------------- kernel 3: L-mix -> exp -> Wm-mix, 2-pass, 256 threads ----------------
__global__ void __launch_bounds__(256)
talk_kernel(const float* __restrict__ Lm, const float* __restrict__ Wmm) {
    extern __shared__ float s[];                 // [16][2048] fp32
    __shared__ float sL[256], sWp[256];
    __shared__ float red[16 * 8];
    __shared__ float ginv[16];

    int tid = threadIdx.x;
    int lane = tid & 31, wid = tid >> 5;
    int bn = blockIdx.x;
    int b = bn >> 11, n = bn & (Nc - 1);
    const size_t HSTRIDE = (size_t)Nc * Nc;
    size_t base = ((size_t)b * Hc) * HSTRIDE + (size_t)n * Nc;

    sL[tid] = Lm[tid];
    for (int idx = tid; idx < Hc * (Nc / 8); idx += 256) {
        int h = idx >> 8, c8 = (idx & 255) * 8;
        uint4 u = *(const uint4*)&g_s[base + (size_t)h * HSTRIDE + c8];
        float2 f0 = __half22float2(*(__half2*)&u.x);
        float2 f1 = __half22float2(*(__half2*)&u.y);
        float2 f2 = __half22float2(*(__half2*)&u.z);
        float2 f3 = __half22float2(*(__half2*)&u.w);
        float4* d = (float4*)&s[h * Nc + c8];
        d[0] = make_float4(f0.x, f0.y, f1.x, f1.y);
        d[1] = make_float4(f2.x, f2.y, f3.x, f3.y);
    }
    __syncthreads();

    float lsum[16];
#pragma unroll
    for (int g = 0; g < 16; g++) lsum[g] = 0.f;
    for (int j = 0; j < Nc / 256; j++) {
        int m = tid + j * 256;
        float sv[16], pv[16];
#pragma unroll
        for (int h = 0; h < 16; h++) sv[h] = s[h * Nc + m];
#pragma unroll
        for (int g = 0; g < 16; g++) {
            float t = -8.0f;
#pragma unroll
            for (int h = 0; h < 16; h++) t = fmaf(sL[g * 16 + h], sv[h], t);
            float p = exp_fast(t);
            lsum[g] += p;
            pv[g] = p;
        }
#pragma unroll
        for (int g = 0; g < 16; g++) s[g * Nc + m] = pv[g];
    }
#pragma unroll
    for (int g = 0; g < 16; g++) {
        float v = lsum[g];
        for (int o = 16; o; o >>= 1) v += __shfl_xor_sync(0xFFFFFFFFu, v, o);
        if (lane == 0) red[g * 8 + wid] = v;
    }
    __syncthreads();
    if (tid < 16) {
        float v = 0.f;
#pragma unroll
        for (int w = 0; w < 8; w++) v += red[tid * 8 + w];
        ginv[tid] = 1.0f / v;
    }
    __syncthreads();
    sWp[tid] = Wmm[tid] * ginv[tid & 15];
    __syncthreads();

    for (int j = 0; j < Nc / 256; j++) {
        int m = tid + j * 256;
        float pv[16];
#pragma unroll
        for (int g = 0; g < 16; g++) pv[g] = s[g * Nc + m];
#pragma unroll
        for (int g2 = 0; g2 < 16; g2++) {
            float u = 0.f;
#pragma unroll
            for (int g = 0; g < 16; g++) u = fmaf(sWp[g2 * 16 + g], pv[g], u);
            g_s[base + (size_t)g2 * HSTRIDE + m] = __float2half_rn(u);
        }
    }
}

// =======================================================================
// kernel 4: O = attn @ V per (b,g). cp.async 2-stage, BK=64. (round-10 proven)
// =======================================================================
#define AV_ASTG (128 * ROWW)
#define AV_BSTG (64 * ROWW)
__global__ void __launch_bounds__(256) av_f16() {
    extern __shared__ uint32_t sm[];
    uint32_t* Am = sm;
    uint32_t* Bm = sm + 2 * AV_ASTG;
    int bh_ = blockIdx.y;
    const __half* U = g_s + (size_t)bh_ * Nc * Nc;
    const __half* Vt = g_v + (size_t)bh_ * Nc * HDc;  // [d][m]

    int tid = threadIdx.x, lane = tid & 31, w = tid >> 5;
    int wm = (w >> 1) * 32, wn = (w & 1) * 32;
    int row0 = blockIdx.x * 128;

    float acc[2][4][4];
#pragma unroll
    for (int a = 0; a < 2; a++)
#pragma unroll
        for (int b = 0; b < 4; b++)
#pragma unroll
            for (int c = 0; c < 4; c++) acc[a][b][c] = 0.f;

    auto load_stage = [&](int s, int kt) {
#pragma unroll
        for (int c = 0; c < 4; c++) {
            int idx = tid + c * 256;
            int m = idx >> 3, ch = idx & 7;
            cpa16(&Am[s * AV_ASTG + m * ROWW + ch * 4],
                  &U[(size_t)(row0 + m) * Nc + kt + ch * 8]);
        }
#pragma unroll
        for (int c = 0; c < 2; c++) {
            int idx = tid + c * 256;
            int d = idx >> 3, ch = idx & 7;
            cpa16(&Bm[s * AV_BSTG + d * ROWW + ch * 4],
                  &Vt[(size_t)d * Nc + kt + ch * 8]);
        }
        cpa_commit();
    };

    load_stage(0, 0);
    const int NI = Nc / 64;  // 32
    for (int i = 0; i < NI; i++) {
        int s = i & 1;
        if (i + 1 < NI) { load_stage(s ^ 1, (i + 1) * 64); cpa_wait1(); }
        else cpa_wait0();
        __syncthreads();
        int kr = lane & 3, rr = lane >> 2;
        const uint32_t* As = Am + s * AV_ASTG;
        const uint32_t* Bs = Bm + s * AV_BSTG;
#pragma unroll
        for (int kk = 0; kk < 4; kk++) {
            int kpb = kk * 8;
            uint32_t ah[2][4], bh[4][2];
#pragma unroll
            for (int mi = 0; mi < 2; mi++) {
                int rb = wm + mi * 16 + rr;
                ah[mi][0] = As[rb * ROWW + kpb + kr];
                ah[mi][1] = As[(rb + 8) * ROWW + kpb + kr];
                ah[mi][2] = As[rb * ROWW + kpb + kr + 4];
                ah[mi][3] = As[(rb + 8) * ROWW + kpb + kr + 4];
            }
#pragma unroll
            for (int ni = 0; ni < 4; ni++) {
                int dn = wn + ni * 8 + rr;
                bh[ni][0] = Bs[dn * ROWW + kpb + kr];
                bh[ni][1] = Bs[dn * ROWW + kpb + kr + 4];
            }
#pragma unroll
            for (int mi = 0; mi < 2; mi++)
#pragma unroll
                for (int ni = 0; ni < 4; ni++) {
                    float* c = acc[mi][ni];
                    mma16(c[0], c[1], c[2], c[3], ah[mi][0], ah[mi][1], ah[mi][2], ah[mi][3], bh[ni][0], bh[ni][1]);
                }
        }
        __syncthreads();
    }
    int b = bh_ >> 4, g = bh_ & 15;
#pragma unroll
    for (int mi = 0; mi < 2; mi++) {
        int r0 = row0 + wm + mi * 16 + (lane >> 2);
        int r1 = r0 + 8;
#pragma unroll
        for (int ni = 0; ni < 4; ni++) {
            int d = wn + ni * 8 + (lane & 3) * 2;
            *(__half2*)&g_o[((size_t)b * Nc + r0) * (Hc * HDc) + g * HDc + d] =
                __floats2half2_rn(acc[mi][ni][0], acc[mi][ni][1]);
            *(__half2*)&g_o[((size_t)b * Nc + r1) * (Hc * HDc) + g * HDc + d] =
                __floats2half2_rn(acc[mi][ni][2], acc[mi][ni][3]);
        }
    }
}
#define AV_SMEM ((2 * AV_ASTG + 2 * AV_BSTG) * 4)

// =======================================================================
// kernel 5: out = g_o @ Wo^T + bo. cp.async 2-stage BK=64, fp16.
// =======================================================================
__global__ void __launch_bounds__(256)
out_f16(const float* __restrict__ bo, float* __restrict__ out) {
    extern __shared__ uint32_t sm[];
    uint32_t* Am = sm;
    uint32_t* Bm = sm + 2 * P_STG;
    int tid = threadIdx.x, lane = tid & 31, w = tid >> 5;
    int wm = (w & 1) * 64, wn = (w >> 1) * 32;
    int row0 = blockIdx.y * 128, col0 = blockIdx.x * 128;

    float acc[4][4][4];
#pragma unroll
    for (int a = 0; a < 4; a++)
#pragma unroll
        for (int b = 0; b < 4; b++)
#pragma unroll
            for (int c = 0; c < 4; c++) acc[a][b][c] = 0.f;

    auto load_stage = [&](int s, int kt) {
#pragma unroll
        for (int c = 0; c < 4; c++) {
            int idx = tid + c * 256;
            int m = idx >> 3, ch = idx & 7;
            cpa16(&Am[s * P_STG + m * ROWW + ch * 4],
                  &g_o[(size_t)(row0 + m) * (Hc * HDc) + kt + ch * 8]);
        }
#pragma unroll
        for (int c = 0; c < 4; c++) {
            int idx = tid + c * 256;
            int n = idx >> 3, ch = idx & 7;
            cpa16(&Bm[s * P_STG + n * ROWW + ch * 4],
                  &g_wo16[(size_t)(col0 + n) * Dc + kt + ch * 8]);
        }
        cpa_commit();
    };

    load_stage(0, 0);
    const int NI = (Hc * HDc) / 64;  // 16
    for (int i = 0; i < NI; i++) {
        int s = i & 1;
        if (i + 1 < NI) { load_stage(s ^ 1, (i + 1) * 64); cpa_wait1(); }
        else cpa_wait0();
        __syncthreads();
        int kr = lane & 3, rr = lane >> 2;
        const uint32_t* As = Am + s * P_STG;
        const uint32_t* Bs = Bm + s * P_STG;
#pragma unroll
        for (int kk = 0; kk < 4; kk++) {
            int kpb = kk * 8;
            uint32_t ah[4][4], bh[4][2];
#pragma unroll
            for (int mi = 0; mi < 4; mi++) {
                int rb = wm + mi * 16 + rr;
                ah[mi][0] = As[rb * ROWW + kpb + kr];
                ah[mi][1] = As[(rb + 8) * ROWW + kpb + kr];
                ah[mi][2] = As[rb * ROWW + kpb + kr + 4];
                ah[mi][3] = As[(rb + 8) * ROWW + kpb + kr + 4];
            }
#pragma unroll
            for (int ni = 0; ni < 4; ni++) {
                int nb = wn + ni * 8 + rr;
                bh[ni][0] = Bs[nb * ROWW + kpb + kr];
                bh[ni][1] = Bs[nb * ROWW + kpb + kr + 4];
            }
#pragma unroll
            for (int mi = 0; mi < 4; mi++)
#pragma unroll
                for (int ni = 0; ni < 4; ni++) {
                    float* c = acc[mi][ni];
                    mma16(c[0], c[1], c[2], c[3], ah[mi][0], ah[mi][1], ah[mi][2], ah[mi][3], bh[ni][0], bh[ni][1]);
                }
        }
        __syncthreads();
    }
#pragma unroll
    for (int mi = 0; mi < 4; mi++) {
        int r0 = row0 + wm + mi * 16 + (lane >> 2);
        int r1 = r0 + 8;
#pragma unroll
        for (int ni = 0; ni < 4; ni++) {
            int c = col0 + wn + ni * 8 + (lane & 3) * 2;
            float2 bias = {bo[c], bo[c + 1]};
            float2 v0 = {acc[mi][ni][0] + bias.x, acc[mi][ni][1] + bias.y};
            float2 v1 = {acc[mi][ni][2] + bias.x, acc[mi][ni][3] + bias.y};
            *(float2*)&out[(size_t)r0 * Dc + c] = v0;
            *(float2*)&out[(size_t)r1 * Dc + c] = v1;
        }
    }
}

// ---------------- launch ----------------
extern "C" void kernel_launch(void* const* d_in, const int* in_sizes, int n_in,
                              void* d_out, int out_size) {
    const float* x  = (const float*)d_in[0];
    const float* Wq = (const float*)d_in[1];
    const float* Wk = (const float*)d_in[2];
    const float* Wv = (const float*)d_in[3];
    const float* L  = (const float*)d_in[4];
    const float* Wm = (const float*)d_in[5];
    const float* Wo = (const float*)d_in[6];
    const float* bo = (const float*)d_in[7];
    float* out = (float*)d_out;
    (void)in_sizes; (void)n_in; (void)out_size;

    // 0) convert to fp16 (x straight; weights transposed, Wk pre-scaled)
    xconv<<<(Bc * Nc * Dc) / 4 / 256, 256>>>(x);
    wconv<<<dim3(32, 32, 4), 256>>>(Wq, Wk, Wv, Wo);

    // 1) QKV projections (cp.async BK=64)
    (void)cudaFuncSetAttribute(proj_f16, cudaFuncAttributeMaxDynamicSharedMemorySize, P_SMEM);
    proj_f16<<<dim3((Hc * HDc) / 128, (Bc * Nc) / 128, 3), 256, P_SMEM>>>();

    // 2) scores (single-stage cp.async)
    scores_f16<<<dim3(Nc / 128, Nc / 128, Bc * Hc), 256>>>();

    // 3) fused talking-heads softmax
    const int TALK_SMEM = Hc * Nc * sizeof(float);  // 128KB
    (void)cudaFuncSetAttribute(talk_kernel, cudaFuncAttributeMaxDynamicSharedMemorySize, TALK_SMEM);
    talk_kernel<<<Bc * Nc, 256, TALK_SMEM>>>(L, Wm);

    // 4) attn @ V (cp.async BK=64)
    (void)cudaFuncSetAttribute(av_f16, cudaFuncAttributeMaxDynamicSharedMemorySize, AV_SMEM);
    av_f16<<<dim3(Nc / 128, Bc * Hc), 256, AV_SMEM>>>();

    // 5) final projection + bias (cp.async BK=64)
    (void)cudaFuncSetAttribute(out_f16, cudaFuncAttributeMaxDynamicSharedMemorySize, P_SMEM);
    out_f16<<<dim3(Dc / 128, (Bc * Nc) / 128), 256, P_SMEM>>>(bo, out);
}

// round 14
// speedup vs baseline: 2.3840x; 1.0504x over previous
#include <cuda_runtime.h>
#include <cuda_fp16.h>
#include <cstdint>

// B=2, N=2048, D=1024, H=16, HD=64
#define Bc 2
#define Nc 2048
#define Dc 1024
#define Hc 16
#define HDc 64

// ---------------- scratch ----------------
__device__ __half g_x16[(size_t)Bc * Nc * Dc];       // x in fp16
__device__ __half g_wq16[(size_t)Dc * Dc];           // W^T fp16 [n][k]
__device__ __half g_wk16[(size_t)Dc * Dc];           // pre-scaled 0.125
__device__ __half g_wv16[(size_t)Dc * Dc];
__device__ __half g_wo16[(size_t)Dc * Dc];
__device__ __half g_q[(size_t)Bc * Hc * Nc * HDc];
__device__ __half g_k[(size_t)Bc * Hc * Nc * HDc];
__device__ __half g_v[(size_t)Bc * Hc * Nc * HDc];   // TRANSPOSED: [b,h,d,n]
__device__ __half g_s[(size_t)Bc * Hc * Nc * Nc];    // 268MB, in-place
__device__ __half g_o[(size_t)Bc * Nc * Hc * HDc];

// ---------------- helpers ----------------
__device__ __forceinline__ void mma16(float& c0, float& c1, float& c2, float& c3,
                                      uint32_t a0, uint32_t a1, uint32_t a2, uint32_t a3,
                                      uint32_t b0, uint32_t b1) {
    asm volatile(
        "mma.sync.aligned.m16n8k16.row.col.f32.f16.f16.f32 "
        "{%0,%1,%2,%3}, {%4,%5,%6,%7}, {%8,%9}, {%0,%1,%2,%3};"
        : "+f"(c0), "+f"(c1), "+f"(c2), "+f"(c3)
        : "r"(a0), "r"(a1), "r"(a2), "r"(a3), "r"(b0), "r"(b1));
}
__device__ __forceinline__ void cpa16(void* dst, const void* src) {
    uint32_t d = (uint32_t)__cvta_generic_to_shared(dst);
    asm volatile("cp.async.ca.shared.global [%0], [%1], 16;" :: "r"(d), "l"(src));
}
__device__ __forceinline__ void cpa_commit() { asm volatile("cp.async.commit_group;"); }
__device__ __forceinline__ void cpa_wait1() { asm volatile("cp.async.wait_group 1;"); }
__device__ __forceinline__ void cpa_wait0() { asm volatile("cp.async.wait_group 0;"); }
__device__ __forceinline__ float ex2f(float x) {
    float r;
    asm("ex2.approx.f32 %0, %1;" : "=f"(r) : "f"(x));
    return r;
}

#define ROWW 36   // smem row stride in words (32 data + 4 pad): conflict-free

// =======================================================================
// kernel 0a: x -> fp16
// =======================================================================
__global__ void __launch_bounds__(256) xconv(const float* __restrict__ x) {
    size_t i = (size_t)blockIdx.x * 256 + threadIdx.x;
    float4 v = ((const float4*)x)[i];
    ((__half2*)g_x16)[2 * i]     = __floats2half2_rn(v.x, v.y);
    ((__half2*)g_x16)[2 * i + 1] = __floats2half2_rn(v.z, v.w);
}

// =======================================================================
// kernel 0b: weights -> fp16 transposed [n][k]; Wk gets 0.125 (exact pow2)
// =======================================================================
__global__ void __launch_bounds__(256) wconv(const float* __restrict__ Wq,
                                             const float* __restrict__ Wk,
                                             const float* __restrict__ Wv,
                                             const float* __restrict__ Wo) {
    __shared__ float t[32][33];
    int which = blockIdx.z;
    const float* src = which == 0 ? Wq : (which == 1 ? Wk : (which == 2 ? Wv : Wo));
    __half* dst = which == 0 ? g_wq16 : (which == 1 ? g_wk16 : (which == 2 ? g_wv16 : g_wo16));
    float sc = (which == 1) ? 0.125f : 1.0f;
    int k0 = blockIdx.y * 32, n0 = blockIdx.x * 32;
    int tx = threadIdx.x & 31, tg = threadIdx.x >> 5;   // 32 x 8
#pragma unroll
    for (int i = 0; i < 4; i++) {
        int ty = tg * 4 + i;
        t[ty][tx] = src[(size_t)(k0 + ty) * Dc + n0 + tx];
    }
    __syncthreads();
#pragma unroll
    for (int i = 0; i < 4; i++) {
        int ty = tg * 4 + i;
        dst[(size_t)(n0 + ty) * Dc + k0 + tx] = __float2half_rn(t[tx][ty] * sc);
    }
}

// =======================================================================
// kernel 1: QKV projections. cp.async 2-stage BK=64 pipeline, all fp16.
// =======================================================================
#define P_STG (128 * ROWW)
__global__ void __launch_bounds__(256) proj_f16() {
    extern __shared__ uint32_t sm[];
    uint32_t* Am = sm;
    uint32_t* Bm = sm + 2 * P_STG;
    int which = blockIdx.z;
    const __half* Wt = which == 0 ? g_wq16 : (which == 1 ? g_wk16 : g_wv16);
    __half* dst = which == 0 ? g_q : (which == 1 ? g_k : g_v);

    int tid = threadIdx.x, lane = tid & 31, w = tid >> 5;
    int wm = (w & 1) * 64, wn = (w >> 1) * 32;
    int row0 = blockIdx.y * 128, col0 = blockIdx.x * 128;

    float acc[4][4][4];
#pragma unroll
    for (int a = 0; a < 4; a++)
#pragma unroll
        for (int b = 0; b < 4; b++)
#pragma unroll
            for (int c = 0; c < 4; c++) acc[a][b][c] = 0.f;

    auto load_stage = [&](int s, int kt) {
#pragma unroll
        for (int c = 0; c < 4; c++) {
            int idx = tid + c * 256;
            int m = idx >> 3, ch = idx & 7;
            cpa16(&Am[s * P_STG + m * ROWW + ch * 4],
                  &g_x16[(size_t)(row0 + m) * Dc + kt + ch * 8]);
        }
#pragma unroll
        for (int c = 0; c < 4; c++) {
            int idx = tid + c * 256;
            int n = idx >> 3, ch = idx & 7;
            cpa16(&Bm[s * P_STG + n * ROWW + ch * 4],
                  &Wt[(size_t)(col0 + n) * Dc + kt + ch * 8]);
        }
        cpa_commit();
    };

    load_stage(0, 0);
    const int NI = Dc / 64;  // 16
    for (int i = 0; i < NI; i++) {
        int s = i & 1;
        if (i + 1 < NI) { load_stage(s ^ 1, (i + 1) * 64); cpa_wait1(); }
        else cpa_wait0();
        __syncthreads();
        int kr = lane & 3, rr = lane >> 2;
        const uint32_t* As = Am + s * P_STG;
        const uint32_t* Bs = Bm + s * P_STG;
#pragma unroll
        for (int kk = 0; kk < 4; kk++) {
            int kpb = kk * 8;
            uint32_t ah[4][4], bh[4][2];
#pragma unroll
            for (int mi = 0; mi < 4; mi++) {
                int rb = wm + mi * 16 + rr;
                ah[mi][0] = As[rb * ROWW + kpb + kr];
                ah[mi][1] = As[(rb + 8) * ROWW + kpb + kr];
                ah[mi][2] = As[rb * ROWW + kpb + kr + 4];
                ah[mi][3] = As[(rb + 8) * ROWW + kpb + kr + 4];
            }
#pragma unroll
            for (int ni = 0; ni < 4; ni++) {
                int nb = wn + ni * 8 + rr;
                bh[ni][0] = Bs[nb * ROWW + kpb + kr];
                bh[ni][1] = Bs[nb * ROWW + kpb + kr + 4];
            }
#pragma unroll
            for (int mi = 0; mi < 4; mi++)
#pragma unroll
                for (int ni = 0; ni < 4; ni++) {
                    float* c = acc[mi][ni];
                    mma16(c[0], c[1], c[2], c[3], ah[mi][0], ah[mi][1], ah[mi][2], ah[mi][3], bh[ni][0], bh[ni][1]);
                }
        }
        __syncthreads();
    }
#pragma unroll
    for (int mi = 0; mi < 4; mi++) {
        int r0 = row0 + wm + mi * 16 + (lane >> 2);
        int r1 = r0 + 8;
        int b0i = r0 >> 11, n0i = r0 & (Nc - 1);
        int b1i = r1 >> 11, n1i = r1 & (Nc - 1);
#pragma unroll
        for (int ni = 0; ni < 4; ni++) {
            int c = col0 + wn + ni * 8 + (lane & 3) * 2;
            int h = c >> 6, d = c & 63;
            if (which == 2) {
                size_t base0 = (size_t)(b0i * Hc + h) * HDc;
                size_t base1 = (size_t)(b1i * Hc + h) * HDc;
                dst[(base0 + d) * Nc + n0i]     = __float2half_rn(acc[mi][ni][0]);
                dst[(base0 + d + 1) * Nc + n0i] = __float2half_rn(acc[mi][ni][1]);
                dst[(base1 + d) * Nc + n1i]     = __float2half_rn(acc[mi][ni][2]);
                dst[(base1 + d + 1) * Nc + n1i] = __float2half_rn(acc[mi][ni][3]);
            } else {
                *(__half2*)&dst[(((size_t)b0i * Hc + h) * Nc + n0i) * HDc + d] =
                    __floats2half2_rn(acc[mi][ni][0], acc[mi][ni][1]);
                *(__half2*)&dst[(((size_t)b1i * Hc + h) * Nc + n1i) * HDc + d] =
                    __floats2half2_rn(acc[mi][ni][2], acc[mi][ni][3]);
            }
        }
    }
}
#define P_SMEM (4 * P_STG * 4)

// =======================================================================
// kernel 2: S = Q K^T per (b,h). Single-stage cp.async, K=64 (one barrier).
// =======================================================================
__global__ void __launch_bounds__(256) scores_f16() {
    __shared__ uint32_t As[128 * ROWW], Bs[128 * ROWW];
    int bh_ = blockIdx.z;
    const __half* Q = g_q + (size_t)bh_ * Nc * HDc;
    const __half* Kc = g_k + (size_t)bh_ * Nc * HDc;

    int tid = threadIdx.x, lane = tid & 31, w = tid >> 5;
    int wm = (w & 1) * 64, wn = (w >> 1) * 32;
    int row0 = blockIdx.y * 128, col0 = blockIdx.x * 128;

#pragma unroll
    for (int c = 0; c < 4; c++) {
        int idx = tid + c * 256;
        int m = idx >> 3, ch = idx & 7;
        cpa16(&As[m * ROWW + ch * 4], &Q[(size_t)(row0 + m) * HDc + ch * 8]);
    }
#pragma unroll
    for (int c = 0; c < 4; c++) {
        int idx = tid + c * 256;
        int n = idx >> 3, ch = idx & 7;
        cpa16(&Bs[n * ROWW + ch * 4], &Kc[(size_t)(col0 + n) * HDc + ch * 8]);
    }
    cpa_commit();
    cpa_wait0();
    __syncthreads();

    float acc[4][4][4];
#pragma unroll
    for (int a = 0; a < 4; a++)
#pragma unroll
        for (int b = 0; b < 4; b++)
#pragma unroll
            for (int c = 0; c < 4; c++) acc[a][b][c] = 0.f;

    int kr = lane & 3, rr = lane >> 2;
#pragma unroll
    for (int kk = 0; kk < 4; kk++) {
        int kpb = kk * 8;
        uint32_t ah[4][4], bh[4][2];
#pragma unroll
        for (int mi = 0; mi < 4; mi++) {
            int rb = wm + mi * 16 + rr;
            ah[mi][0] = As[rb * ROWW + kpb + kr];
            ah[mi][1] = As[(rb + 8) * ROWW + kpb + kr];
            ah[mi][2] = As[rb * ROWW + kpb + kr + 4];
            ah[mi][3] = As[(rb + 8) * ROWW + kpb + kr + 4];
        }
#pragma unroll
        for (int ni = 0; ni < 4; ni++) {
            int nb = wn + ni * 8 + rr;
            bh[ni][0] = Bs[nb * ROWW + kpb + kr];
            bh[ni][1] = Bs[nb * ROWW + kpb + kr + 4];
        }
#pragma unroll
        for (int mi = 0; mi < 4; mi++)
#pragma unroll
            for (int ni = 0; ni < 4; ni++) {
                float* c = acc[mi][ni];
                mma16(c[0], c[1], c[2], c[3], ah[mi][0], ah[mi][1], ah[mi][2], ah[mi][3], bh[ni][0], bh[ni][1]);
            }
    }
    size_t base = (size_t)bh_ * Nc * Nc;
#pragma unroll
    for (int mi = 0; mi < 4; mi++) {
        int r0 = row0 + wm + mi * 16 + (lane >> 2);
        int r1 = r0 + 8;
#pragma unroll
        for (int ni = 0; ni < 4; ni++) {
            int c = col0 + wn + ni * 8 + (lane & 3) * 2;
            *(__half2*)&g_s[base + (size_t)r0 * Nc + c] = __floats2half2_rn(acc[mi][ni][0], acc[mi][ni][1]);
            *(__half2*)&g_s[base + (size_t)r1 * Nc + c] = __floats2half2_rn(acc[mi][ni][2], acc[mi][ni][3]);
        }
    }
}

// =======================================================================
// kernel 3: talking-heads softmax. fp16 smem (64KB, 2 CTAs/SM), ex2 on MUFU.
// sL pre-multiplied by log2(e); shift -8*log2(e) cancels exactly in softmax.
// p stored fp16 in smem (adds ~3e-4 in quadrature; still << 1e-3).
// =======================================================================
__global__ void __launch_bounds__(256, 2)
talk_kernel(const float* __restrict__ Lm, const float* __restrict__ Wmm) {
    extern __shared__ __half2 s2[];              // [16][1024] half2 = 64KB
    __shared__ float sL[256], sWp[256];
    __shared__ float red[16 * 8];
    __shared__ float ginv[16];

    int tid = threadIdx.x;                       // 256 threads, 8 warps
    int lane = tid & 31, wid = tid >> 5;
    int bn = blockIdx.x;
    int b = bn >> 11, n = bn & (Nc - 1);
    const size_t HSTRIDE = (size_t)Nc * Nc;
    size_t base = ((size_t)b * Hc) * HSTRIDE + (size_t)n * Nc;

    sL[tid] = Lm[tid] * 1.44269504f;             // fold log2(e) into L
    // pure fp16 tile copy via cp.async: 16 rows x 256 uint4
#pragma unroll
    for (int c = 0; c < 16; c++) {
        int idx = tid + c * 256;
        int h = idx >> 8, c8 = idx & 255;
        cpa16(&s2[h * 1024 + c8 * 4], &g_s[base + (size_t)h * HSTRIDE + c8 * 8]);
    }
    cpa_commit();
    cpa_wait0();
    __syncthreads();

    // ---- pass A: t = (L*S)*log2e - 11.54; p = 2^t; accumulate sums ----
    float lx[16], ly[16];
#pragma unroll
    for (int g = 0; g < 16; g++) { lx[g] = 0.f; ly[g] = 0.f; }
    for (int j = 0; j < 4; j++) {                // 1024 half2 cols / 256 thr
        int m2 = tid + j * 256;
        float2 sv[16];
#pragma unroll
        for (int h = 0; h < 16; h++) sv[h] = __half22float2(s2[h * 1024 + m2]);
#pragma unroll
        for (int g = 0; g < 16; g++) {
            float tx = -11.5415603f, ty = -11.5415603f;   // 8*log2(e)
#pragma unroll
            for (int h = 0; h < 16; h++) {
                tx = fmaf(sL[g * 16 + h], sv[h].x, tx);
                ty = fmaf(sL[g * 16 + h], sv[h].y, ty);
            }
            float px = ex2f(tx), py = ex2f(ty);
            lx[g] += px; ly[g] += py;
            s2[g * 1024 + m2] = __floats2half2_rn(px, py);
        }
    }
#pragma unroll
    for (int g = 0; g < 16; g++) {
        float v = lx[g] + ly[g];
        for (int o = 16; o; o >>= 1) v += __shfl_xor_sync(0xFFFFFFFFu, v, o);
        if (lane == 0) red[g * 8 + wid] = v;
    }
    __syncthreads();
    if (tid < 16) {
        float v = 0.f;
#pragma unroll
        for (int w = 0; w < 8; w++) v += red[tid * 8 + w];
        ginv[tid] = 1.0f / v;
    }
    __syncthreads();
    sWp[tid] = Wmm[tid] * ginv[tid & 15];
    __syncthreads();

    // ---- pass B: U = Wm'*p, write fp16 gmem ----
    for (int j = 0; j < 4; j++) {
        int m2 = tid + j * 256;
        float2 pv[16];
#pragma unroll
        for (int g = 0; g < 16; g++) pv[g] = __half22float2(s2[g * 1024 + m2]);
#pragma unroll
        for (int g2 = 0; g2 < 16; g2++) {
            float ux = 0.f, uy = 0.f;
#pragma unroll
            for (int g = 0; g < 16; g++) {
                ux = fmaf(sWp[g2 * 16 + g], pv[g].x, ux);
                uy = fmaf(sWp[g2 * 16 + g], pv[g].y, uy);
            }
            *(__half2*)&g_s[base + (size_t)g2 * HSTRIDE + 2 * m2] = __floats2half2_rn(ux, uy);
        }
    }
}

// =======================================================================
// kernel 4: O = attn @ V per (b,g). cp.async 2-stage, BK=64. (round-10 proven)
// =======================================================================
#define AV_ASTG (128 * ROWW)
#define AV_BSTG (64 * ROWW)
__global__ void __launch_bounds__(256) av_f16() {
    extern __shared__ uint32_t sm[];
    uint32_t* Am = sm;
    uint32_t* Bm = sm + 2 * AV_ASTG;
    int bh_ = blockIdx.y;
    const __half* U = g_s + (size_t)bh_ * Nc * Nc;
    const __half* Vt = g_v + (size_t)bh_ * Nc * HDc;  // [d][m]

    int tid = threadIdx.x, lane = tid & 31, w = tid >> 5;
    int wm = (w >> 1) * 32, wn = (w & 1) * 32;
    int row0 = blockIdx.x * 128;

    float acc[2][4][4];
#pragma unroll
    for (int a = 0; a < 2; a++)
#pragma unroll
        for (int b = 0; b < 4; b++)
#pragma unroll
            for (int c = 0; c < 4; c++) acc[a][b][c] = 0.f;

    auto load_stage = [&](int s, int kt) {
#pragma unroll
        for (int c = 0; c < 4; c++) {
            int idx = tid + c * 256;
            int m = idx >> 3, ch = idx & 7;
            cpa16(&Am[s * AV_ASTG + m * ROWW + ch * 4],
                  &U[(size_t)(row0 + m) * Nc + kt + ch * 8]);
        }
#pragma unroll
        for (int c = 0; c < 2; c++) {
            int idx = tid + c * 256;
            int d = idx >> 3, ch = idx & 7;
            cpa16(&Bm[s * AV_BSTG + d * ROWW + ch * 4],
                  &Vt[(size_t)d * Nc + kt + ch * 8]);
        }
        cpa_commit();
    };

    load_stage(0, 0);
    const int NI = Nc / 64;  // 32
    for (int i = 0; i < NI; i++) {
        int s = i & 1;
        if (i + 1 < NI) { load_stage(s ^ 1, (i + 1) * 64); cpa_wait1(); }
        else cpa_wait0();
        __syncthreads();
        int kr = lane & 3, rr = lane >> 2;
        const uint32_t* As = Am + s * AV_ASTG;
        const uint32_t* Bs = Bm + s * AV_BSTG;
#pragma unroll
        for (int kk = 0; kk < 4; kk++) {
            int kpb = kk * 8;
            uint32_t ah[2][4], bh[4][2];
#pragma unroll
            for (int mi = 0; mi < 2; mi++) {
                int rb = wm + mi * 16 + rr;
                ah[mi][0] = As[rb * ROWW + kpb + kr];
                ah[mi][1] = As[(rb + 8) * ROWW + kpb + kr];
                ah[mi][2] = As[rb * ROWW + kpb + kr + 4];
                ah[mi][3] = As[(rb + 8) * ROWW + kpb + kr + 4];
            }
#pragma unroll
            for (int ni = 0; ni < 4; ni++) {
                int dn = wn + ni * 8 + rr;
                bh[ni][0] = Bs[dn * ROWW + kpb + kr];
                bh[ni][1] = Bs[dn * ROWW + kpb + kr + 4];
            }
#pragma unroll
            for (int mi = 0; mi < 2; mi++)
#pragma unroll
                for (int ni = 0; ni < 4; ni++) {
                    float* c = acc[mi][ni];
                    mma16(c[0], c[1], c[2], c[3], ah[mi][0], ah[mi][1], ah[mi][2], ah[mi][3], bh[ni][0], bh[ni][1]);
                }
        }
        __syncthreads();
    }
    int b = bh_ >> 4, g = bh_ & 15;
#pragma unroll
    for (int mi = 0; mi < 2; mi++) {
        int r0 = row0 + wm + mi * 16 + (lane >> 2);
        int r1 = r0 + 8;
#pragma unroll
        for (int ni = 0; ni < 4; ni++) {
            int d = wn + ni * 8 + (lane & 3) * 2;
            *(__half2*)&g_o[((size_t)b * Nc + r0) * (Hc * HDc) + g * HDc + d] =
                __floats2half2_rn(acc[mi][ni][0], acc[mi][ni][1]);
            *(__half2*)&g_o[((size_t)b * Nc + r1) * (Hc * HDc) + g * HDc + d] =
                __floats2half2_rn(acc[mi][ni][2], acc[mi][ni][3]);
        }
    }
}
#define AV_SMEM ((2 * AV_ASTG + 2 * AV_BSTG) * 4)

// =======================================================================
// kernel 5: out = g_o @ Wo^T + bo. cp.async 2-stage BK=64, fp16.
// =======================================================================
__global__ void __launch_bounds__(256)
out_f16(const float* __restrict__ bo, float* __restrict__ out) {
    extern __shared__ uint32_t sm[];
    uint32_t* Am = sm;
    uint32_t* Bm = sm + 2 * P_STG;
    int tid = threadIdx.x, lane = tid & 31, w = tid >> 5;
    int wm = (w & 1) * 64, wn = (w >> 1) * 32;
    int row0 = blockIdx.y * 128, col0 = blockIdx.x * 128;

    float acc[4][4][4];
#pragma unroll
    for (int a = 0; a < 4; a++)
#pragma unroll
        for (int b = 0; b < 4; b++)
#pragma unroll
            for (int c = 0; c < 4; c++) acc[a][b][c] = 0.f;

    auto load_stage = [&](int s, int kt) {
#pragma unroll
        for (int c = 0; c < 4; c++) {
            int idx = tid + c * 256;
            int m = idx >> 3, ch = idx & 7;
            cpa16(&Am[s * P_STG + m * ROWW + ch * 4],
                  &g_o[(size_t)(row0 + m) * (Hc * HDc) + kt + ch * 8]);
        }
#pragma unroll
        for (int c = 0; c < 4; c++) {
            int idx = tid + c * 256;
            int n = idx >> 3, ch = idx & 7;
            cpa16(&Bm[s * P_STG + n * ROWW + ch * 4],
                  &g_wo16[(size_t)(col0 + n) * Dc + kt + ch * 8]);
        }
        cpa_commit();
    };

    load_stage(0, 0);
    const int NI = (Hc * HDc) / 64;  // 16
    for (int i = 0; i < NI; i++) {
        int s = i & 1;
        if (i + 1 < NI) { load_stage(s ^ 1, (i + 1) * 64); cpa_wait1(); }
        else cpa_wait0();
        __syncthreads();
        int kr = lane & 3, rr = lane >> 2;
        const uint32_t* As = Am + s * P_STG;
        const uint32_t* Bs = Bm + s * P_STG;
#pragma unroll
        for (int kk = 0; kk < 4; kk++) {
            int kpb = kk * 8;
            uint32_t ah[4][4], bh[4][2];
#pragma unroll
            for (int mi = 0; mi < 4; mi++) {
                int rb = wm + mi * 16 + rr;
                ah[mi][0] = As[rb * ROWW + kpb + kr];
                ah[mi][1] = As[(rb + 8) * ROWW + kpb + kr];
                ah[mi][2] = As[rb * ROWW + kpb + kr + 4];
                ah[mi][3] = As[(rb + 8) * ROWW + kpb + kr + 4];
            }
#pragma unroll
            for (int ni = 0; ni < 4; ni++) {
                int nb = wn + ni * 8 + rr;
                bh[ni][0] = Bs[nb * ROWW + kpb + kr];
                bh[ni][1] = Bs[nb * ROWW + kpb + kr + 4];
            }
#pragma unroll
            for (int mi = 0; mi < 4; mi++)
#pragma unroll
                for (int ni = 0; ni < 4; ni++) {
                    float* c = acc[mi][ni];
                    mma16(c[0], c[1], c[2], c[3], ah[mi][0], ah[mi][1], ah[mi][2], ah[mi][3], bh[ni][0], bh[ni][1]);
                }
        }
        __syncthreads();
    }
#pragma unroll
    for (int mi = 0; mi < 4; mi++) {
        int r0 = row0 + wm + mi * 16 + (lane >> 2);
        int r1 = r0 + 8;
#pragma unroll
        for (int ni = 0; ni < 4; ni++) {
            int c = col0 + wn + ni * 8 + (lane & 3) * 2;
            float2 bias = {bo[c], bo[c + 1]};
            float2 v0 = {acc[mi][ni][0] + bias.x, acc[mi][ni][1] + bias.y};
            float2 v1 = {acc[mi][ni][2] + bias.x, acc[mi][ni][3] + bias.y};
            *(float2*)&out[(size_t)r0 * Dc + c] = v0;
            *(float2*)&out[(size_t)r1 * Dc + c] = v1;
        }
    }
}

// ---------------- launch ----------------
extern "C" void kernel_launch(void* const* d_in, const int* in_sizes, int n_in,
                              void* d_out, int out_size) {
    const float* x  = (const float*)d_in[0];
    const float* Wq = (const float*)d_in[1];
    const float* Wk = (const float*)d_in[2];
    const float* Wv = (const float*)d_in[3];
    const float* L  = (const float*)d_in[4];
    const float* Wm = (const float*)d_in[5];
    const float* Wo = (const float*)d_in[6];
    const float* bo = (const float*)d_in[7];
    float* out = (float*)d_out;
    (void)in_sizes; (void)n_in; (void)out_size;

    // 0) convert to fp16 (x straight; weights transposed, Wk pre-scaled)
    xconv<<<(Bc * Nc * Dc) / 4 / 256, 256>>>(x);
    wconv<<<dim3(32, 32, 4), 256>>>(Wq, Wk, Wv, Wo);

    // 1) QKV projections (cp.async BK=64)
    (void)cudaFuncSetAttribute(proj_f16, cudaFuncAttributeMaxDynamicSharedMemorySize, P_SMEM);
    proj_f16<<<dim3((Hc * HDc) / 128, (Bc * Nc) / 128, 3), 256, P_SMEM>>>();

    // 2) scores (single-stage cp.async)
    scores_f16<<<dim3(Nc / 128, Nc / 128, Bc * Hc), 256>>>();

    // 3) fused talking-heads softmax (fp16 smem, 2 CTAs/SM, ex2)
    const int TALK_SMEM = Hc * (Nc / 2) * sizeof(__half2);  // 64KB
    (void)cudaFuncSetAttribute(talk_kernel, cudaFuncAttributeMaxDynamicSharedMemorySize, TALK_SMEM);
    talk_kernel<<<Bc * Nc, 256, TALK_SMEM>>>(L, Wm);

    // 4) attn @ V (cp.async BK=64)
    (void)cudaFuncSetAttribute(av_f16, cudaFuncAttributeMaxDynamicSharedMemorySize, AV_SMEM);
    av_f16<<<dim3(Nc / 128, Bc * Hc), 256, AV_SMEM>>>();

    // 5) final projection + bias (cp.async BK=64)
    (void)cudaFuncSetAttribute(out_f16, cudaFuncAttributeMaxDynamicSharedMemorySize, P_SMEM);
    out_f16<<<dim3(Dc / 128, (Bc * Nc) / 128), 256, P_SMEM>>>(bo, out);
}